// round 1
// baseline (speedup 1.0000x reference)
#include <cuda_runtime.h>
#include <cuda_bf16.h>
#include <math.h>

#define NN 10000
#define EE 320000
#define BB 8
#define SS 12
#define HH 64
#define HEADS 4
#define CC 16
#define LL 3
#define PP 3
#define BN (BB * NN)          // 80000
#define EPSF 1e-5f

// ---------------- scratch (device globals; no allocations allowed) -------------
__device__ __align__(16) float d_h[BN * HH];
__device__ __align__(16) float d_q[BN * HH];
__device__ __align__(16) float d_k[BN * HH];
__device__ __align__(16) float d_v[BN * HH];
__device__ __align__(16) float d_s[BN * HH];
__device__ __align__(16) float d_agg[BN * HH];
__device__ float d_den[BN * HEADS];
__device__ int d_src[EE];
__device__ int d_dst[EE];
__device__ int d_is64;

// ---------------- edge index dtype detect + convert ----------------------------
__global__ void detect_kernel(const void* ei) {
    // if int64 layout, every value (first 64 src entries) is in [0, NN)
    const long long* p = (const long long*)ei;
    int is64 = 1;
    for (int i = 0; i < 64; i++) {
        long long v = p[i];
        if (v < 0 || v >= NN) { is64 = 0; break; }
    }
    d_is64 = is64;
}

__global__ void convert_kernel(const void* ei) {
    int e = blockIdx.x * blockDim.x + threadIdx.x;
    if (e >= EE) return;
    if (d_is64) {
        const long long* p = (const long long*)ei;
        d_src[e] = (int)p[e];
        d_dst[e] = (int)p[EE + e];
    } else {
        const int* p = (const int*)ei;
        d_src[e] = p[e];
        d_dst[e] = p[EE + e];
    }
}

// ---------------- input projection: h[b,n,:] = x[b,:,n] @ in_W + in_b ----------
__global__ void input_proj_kernel(const float* __restrict__ x,
                                  const float* __restrict__ inW,
                                  const float* __restrict__ inb) {
    __shared__ float xs[SS * 64];
    __shared__ float Ws[SS * HH];
    int b = blockIdx.y;
    int nb = blockIdx.x * 64;
    int tid = threadIdx.x;   // 256 threads
    for (int idx = tid; idx < SS * HH; idx += 256) Ws[idx] = inW[idx];
    for (int idx = tid; idx < SS * 64; idx += 256) {
        int s = idx >> 6, i = idx & 63;
        int n = nb + i;
        xs[idx] = (n < NN) ? x[(size_t)b * SS * NN + s * NN + n] : 0.0f;
    }
    __syncthreads();
    int j = tid & 63;
    int i0 = (tid >> 6) * 16;
    float bj = inb[j];
    for (int ii = 0; ii < 16; ii++) {
        int i = i0 + ii;
        int n = nb + i;
        if (n >= NN) break;
        float acc = bj;
#pragma unroll
        for (int s = 0; s < SS; s++) acc += xs[s * 64 + i] * Ws[s * HH + j];
        d_h[((size_t)b * NN + n) * HH + j] = acc;
    }
}

// ---------------- QKVS gemm: out = h @ W + b, sel in {q,k,v,skip} --------------
__global__ void gemm4_kernel(const float* __restrict__ W0, const float* __restrict__ W1,
                             const float* __restrict__ W2, const float* __restrict__ W3,
                             const float* __restrict__ b0, const float* __restrict__ b1,
                             const float* __restrict__ b2, const float* __restrict__ b3) {
    __shared__ float Ws[64 * 64];
    __shared__ float ht[64 * 33];
    int sel = blockIdx.y;
    const float* W = (sel == 0) ? W0 : (sel == 1) ? W1 : (sel == 2) ? W2 : W3;
    const float* bb = (sel == 0) ? b0 : (sel == 1) ? b1 : (sel == 2) ? b2 : b3;
    float* out = (sel == 0) ? d_q : (sel == 1) ? d_k : (sel == 2) ? d_v : d_s;
    int tid = threadIdx.x;   // 128 threads
    int base = blockIdx.x * 32;   // 32 rows per block, BN % 32 == 0
    for (int idx = tid; idx < 4096; idx += 128) Ws[idx] = W[idx];
    for (int idx = tid; idx < 2048; idx += 128) {
        int i = idx >> 6, k = idx & 63;
        ht[k * 33 + i] = d_h[(size_t)(base + i) * 64 + k];
    }
    __syncthreads();
    int ci = tid & 15, ri = tid >> 4;
    int c0 = ci * 4, n0 = ri * 4;
    float acc[4][4] = {};
#pragma unroll 8
    for (int k = 0; k < 64; k++) {
        const float4 wv = *(const float4*)(Ws + k * 64 + c0);
        const float* hp = ht + k * 33 + n0;
        float h0 = hp[0], h1 = hp[1], h2 = hp[2], h3 = hp[3];
        acc[0][0] += h0 * wv.x; acc[0][1] += h0 * wv.y; acc[0][2] += h0 * wv.z; acc[0][3] += h0 * wv.w;
        acc[1][0] += h1 * wv.x; acc[1][1] += h1 * wv.y; acc[1][2] += h1 * wv.z; acc[1][3] += h1 * wv.w;
        acc[2][0] += h2 * wv.x; acc[2][1] += h2 * wv.y; acc[2][2] += h2 * wv.z; acc[2][3] += h2 * wv.w;
        acc[3][0] += h3 * wv.x; acc[3][1] += h3 * wv.y; acc[3][2] += h3 * wv.z; acc[3][3] += h3 * wv.w;
    }
    float4 bv = make_float4(bb[c0], bb[c0 + 1], bb[c0 + 2], bb[c0 + 3]);
#pragma unroll
    for (int i = 0; i < 4; i++) {
        float4 o = make_float4(acc[i][0] + bv.x, acc[i][1] + bv.y,
                               acc[i][2] + bv.z, acc[i][3] + bv.w);
        *(float4*)(out + (size_t)(base + n0 + i) * 64 + c0) = o;
    }
}

// ---------------- zero den + agg ----------------------------------------------
__global__ void zero_kernel() {
    int i = blockIdx.x * blockDim.x + threadIdx.x;   // grid covers BN*HH
    if (i < BN * HH) d_agg[i] = 0.0f;
    if (i < BN * HEADS) d_den[i] = 0.0f;
}

// ---------------- edge pass: softmax-weighted aggregation (no max-shift) -------
// thread = (batch=blockIdx.y, edge, head); 4 consecutive threads share an edge
__global__ void edge_kernel() {
    int b = blockIdx.y;
    int g = blockIdx.x * blockDim.x + threadIdx.x;    // < EE*HEADS (exact)
    int head = g & 3;
    int e = g >> 2;
    int s = d_src[e];
    int d = d_dst[e];
    int qbase = ((b * NN + d) * HEADS + head) * CC;
    int kbase = ((b * NN + s) * HEADS + head) * CC;
    const float4* qp = (const float4*)(d_q + qbase);
    const float4* kp = (const float4*)(d_k + kbase);
    float dotv = 0.0f;
#pragma unroll
    for (int i = 0; i < 4; i++) {
        float4 a = qp[i], c = kp[i];
        dotv += a.x * c.x + a.y * c.y + a.z * c.z + a.w * c.w;
    }
    float w = __expf(dotv * 0.25f);   // 1/sqrt(16)
    atomicAdd(&d_den[(b * NN + d) * HEADS + head], w);
    const float4* vp = (const float4*)(d_v + kbase);
    float4* ap = (float4*)(d_agg + qbase);
#pragma unroll
    for (int i = 0; i < 4; i++) {
        float4 vv = vp[i];
        float4 t = make_float4(vv.x * w, vv.y * w, vv.z * w, vv.w * w);
        atomicAdd(&ap[i], t);
    }
}

// ---------------- node update: h = LN(h + agg/den + skip) ----------------------
__global__ void node_update_kernel(const float* __restrict__ g,
                                   const float* __restrict__ bta) {
    int nid = blockIdx.x * 4 + (threadIdx.x >> 5);   // warp per node
    int lane = threadIdx.x & 31;
    int base = nid * HH;
    float val[2];
#pragma unroll
    for (int t = 0; t < 2; t++) {
        int j = lane + t * 32;
        int head = j >> 4;
        float den = d_den[nid * HEADS + head];
        float inv = (den > 0.0f) ? (1.0f / den) : 0.0f;
        val[t] = d_h[base + j] + d_agg[base + j] * inv + d_s[base + j];
    }
    float sum = val[0] + val[1];
    float sq = val[0] * val[0] + val[1] * val[1];
#pragma unroll
    for (int o = 16; o > 0; o >>= 1) {
        sum += __shfl_xor_sync(0xFFFFFFFF, sum, o);
        sq  += __shfl_xor_sync(0xFFFFFFFF, sq, o);
    }
    float mean = sum * (1.0f / 64.0f);
    float var = sq * (1.0f / 64.0f) - mean * mean;
    float rs = rsqrtf(var + EPSF);
#pragma unroll
    for (int t = 0; t < 2; t++) {
        int j = lane + t * 32;
        d_h[base + j] = (val[t] - mean) * rs * g[j] + bta[j];
    }
}

// ---------------- output projection: out[b,p,n] = h[b,n,:]@out_W + out_b -------
__global__ void out_proj_kernel(const float* __restrict__ oW,
                                const float* __restrict__ ob,
                                float* __restrict__ out) {
    int t = blockIdx.x * blockDim.x + threadIdx.x;
    if (t >= BN) return;
    int b = t / NN, n = t % NN;
    const float4* hr = (const float4*)(d_h + (size_t)t * 64);
    float a0 = ob[0], a1 = ob[1], a2 = ob[2];
#pragma unroll
    for (int i = 0; i < 16; i++) {
        float4 hv = hr[i];
        int h0 = i * 4;
        a0 += hv.x * oW[(h0 + 0) * PP + 0]; a1 += hv.x * oW[(h0 + 0) * PP + 1]; a2 += hv.x * oW[(h0 + 0) * PP + 2];
        a0 += hv.y * oW[(h0 + 1) * PP + 0]; a1 += hv.y * oW[(h0 + 1) * PP + 1]; a2 += hv.y * oW[(h0 + 1) * PP + 2];
        a0 += hv.z * oW[(h0 + 2) * PP + 0]; a1 += hv.z * oW[(h0 + 2) * PP + 1]; a2 += hv.z * oW[(h0 + 2) * PP + 2];
        a0 += hv.w * oW[(h0 + 3) * PP + 0]; a1 += hv.w * oW[(h0 + 3) * PP + 1]; a2 += hv.w * oW[(h0 + 3) * PP + 2];
    }
    out[(size_t)b * PP * NN + 0 * NN + n] = a0;
    out[(size_t)b * PP * NN + 1 * NN + n] = a1;
    out[(size_t)b * PP * NN + 2 * NN + n] = a2;
}

// ---------------- launch --------------------------------------------------------
extern "C" void kernel_launch(void* const* d_in, const int* in_sizes, int n_in,
                              void* d_out, int out_size) {
    const float* x    = (const float*)d_in[0];
    const void*  ei   = d_in[1];
    const float* inW  = (const float*)d_in[2];
    const float* inb  = (const float*)d_in[3];
    const float* Wq   = (const float*)d_in[4];
    const float* bq   = (const float*)d_in[5];
    const float* Wk   = (const float*)d_in[6];
    const float* bk   = (const float*)d_in[7];
    const float* Wv   = (const float*)d_in[8];
    const float* bv   = (const float*)d_in[9];
    const float* Wsk  = (const float*)d_in[10];
    const float* bsk  = (const float*)d_in[11];
    const float* lng  = (const float*)d_in[12];
    const float* lnb  = (const float*)d_in[13];
    const float* oW   = (const float*)d_in[14];
    const float* ob   = (const float*)d_in[15];
    float* out = (float*)d_out;

    detect_kernel<<<1, 1>>>(ei);
    convert_kernel<<<EE / 256, 256>>>(ei);

    dim3 ipg((NN + 63) / 64, BB);
    input_proj_kernel<<<ipg, 256>>>(x, inW, inb);

    for (int l = 0; l < LL; l++) {
        const float* wq = Wq + l * HH * HH; const float* bq_ = bq + l * HH;
        const float* wk = Wk + l * HH * HH; const float* bk_ = bk + l * HH;
        const float* wv = Wv + l * HH * HH; const float* bv_ = bv + l * HH;
        const float* ws = Wsk + l * HH * HH; const float* bs_ = bsk + l * HH;

        dim3 gg(BN / 32, 4);
        gemm4_kernel<<<gg, 128>>>(wq, wk, wv, ws, bq_, bk_, bv_, bs_);

        zero_kernel<<<(BN * HH + 255) / 256, 256>>>();

        dim3 eg(EE * HEADS / 256, BB);
        edge_kernel<<<eg, 256>>>();

        node_update_kernel<<<BN / 4, 128>>>(lng, lnb);
    }

    out_proj_kernel<<<(BN + 255) / 256, 256>>>(oW, ob, out);
}

// round 2
// speedup vs baseline: 1.9636x; 1.9636x over previous
#include <cuda_runtime.h>
#include <cuda_bf16.h>
#include <math.h>

#define NN 10000
#define EE 320000
#define BB 8
#define SS 12
#define HH 64
#define HEADS 4
#define CC 16
#define LL 3
#define PP 3
#define BN (BB * NN)          // 80000
#define EPSF 1e-5f

// ---------------- scratch (device globals; no allocations allowed) -------------
__device__ __align__(16) float d_h[BN * HH];
__device__ __align__(16) float d_q[BN * HH];
__device__ __align__(16) float d_k[BN * HH];
__device__ __align__(16) float d_v[BN * HH];
__device__ __align__(16) float d_s[BN * HH];
__device__ int d_src[EE];
__device__ int d_dst[EE];
__device__ int d_deg[NN];
__device__ int d_ptr[NN + 1];
__device__ int d_cnt[NN];
__device__ int d_csr_src[EE];
__device__ int d_is64;

// ---------------- edge index dtype detect ----------------------------------------
__global__ void detect_kernel(const void* ei) {
    const long long* p = (const long long*)ei;
    int is64 = 1;
    for (int i = 0; i < 64; i++) {
        long long v = p[i];
        if (v < 0 || v >= NN) { is64 = 0; break; }
    }
    d_is64 = is64;
}

__global__ void zero_deg_kernel() {
    int i = blockIdx.x * blockDim.x + threadIdx.x;
    if (i < NN) d_deg[i] = 0;
}

// convert + degree histogram
__global__ void convert_kernel(const void* ei) {
    int e = blockIdx.x * blockDim.x + threadIdx.x;
    if (e >= EE) return;
    int s, d;
    if (d_is64) {
        const long long* p = (const long long*)ei;
        s = (int)p[e];
        d = (int)p[EE + e];
    } else {
        const int* p = (const int*)ei;
        s = p[e];
        d = p[EE + e];
    }
    d_src[e] = s;
    d_dst[e] = d;
    atomicAdd(&d_deg[d], 1);
}

// single-block exclusive scan of d_deg -> d_ptr (and d_cnt copy)
__global__ void scan_kernel() {
    __shared__ int sums[256];
    int tid = threadIdx.x;                 // 256 threads
    const int PER = (NN + 255) / 256;      // 40
    int start = tid * PER;
    int local = 0;
    for (int i = 0; i < PER; i++) {
        int idx = start + i;
        if (idx < NN) local += d_deg[idx];
    }
    sums[tid] = local;
    __syncthreads();
    if (tid == 0) {
        int acc = 0;
        for (int i = 0; i < 256; i++) { int t = sums[i]; sums[i] = acc; acc += t; }
    }
    __syncthreads();
    int acc = sums[tid];
    for (int i = 0; i < PER; i++) {
        int idx = start + i;
        if (idx < NN) {
            d_ptr[idx] = acc;
            d_cnt[idx] = acc;
            acc += d_deg[idx];
        }
    }
    if (tid == 255) d_ptr[NN] = EE;
}

// scatter edges into CSR rows by dst
__global__ void scatter_kernel() {
    int e = blockIdx.x * blockDim.x + threadIdx.x;
    if (e >= EE) return;
    int d = d_dst[e];
    int pos = atomicAdd(&d_cnt[d], 1);
    d_csr_src[pos] = d_src[e];
}

// ---------------- input projection: h[b,n,:] = x[b,:,n] @ in_W + in_b ----------
__global__ void input_proj_kernel(const float* __restrict__ x,
                                  const float* __restrict__ inW,
                                  const float* __restrict__ inb) {
    __shared__ float xs[SS * 64];
    __shared__ float Ws[SS * HH];
    int b = blockIdx.y;
    int nb = blockIdx.x * 64;
    int tid = threadIdx.x;   // 256 threads
    for (int idx = tid; idx < SS * HH; idx += 256) Ws[idx] = inW[idx];
    for (int idx = tid; idx < SS * 64; idx += 256) {
        int s = idx >> 6, i = idx & 63;
        int n = nb + i;
        xs[idx] = (n < NN) ? x[(size_t)b * SS * NN + s * NN + n] : 0.0f;
    }
    __syncthreads();
    int j = tid & 63;
    int i0 = (tid >> 6) * 16;
    float bj = inb[j];
    for (int ii = 0; ii < 16; ii++) {
        int i = i0 + ii;
        int n = nb + i;
        if (n >= NN) break;
        float acc = bj;
#pragma unroll
        for (int s = 0; s < SS; s++) acc += xs[s * 64 + i] * Ws[s * HH + j];
        d_h[((size_t)b * NN + n) * HH + j] = acc;
    }
}

// ---------------- QKVS gemm: out = h @ W + b, sel in {q,k,v,skip} --------------
__global__ void gemm4_kernel(const float* __restrict__ W0, const float* __restrict__ W1,
                             const float* __restrict__ W2, const float* __restrict__ W3,
                             const float* __restrict__ b0, const float* __restrict__ b1,
                             const float* __restrict__ b2, const float* __restrict__ b3) {
    __shared__ float Ws[64 * 64];
    __shared__ float ht[64 * 36];          // padded stride 36 -> float4-aligned rows
    int sel = blockIdx.y;
    const float* W = (sel == 0) ? W0 : (sel == 1) ? W1 : (sel == 2) ? W2 : W3;
    const float* bb = (sel == 0) ? b0 : (sel == 1) ? b1 : (sel == 2) ? b2 : b3;
    float* out = (sel == 0) ? d_q : (sel == 1) ? d_k : (sel == 2) ? d_v : d_s;
    int tid = threadIdx.x;   // 128 threads
    int base = blockIdx.x * 32;
    for (int idx = tid; idx < 4096; idx += 128) Ws[idx] = W[idx];
    for (int idx = tid; idx < 2048; idx += 128) {
        int i = idx >> 6, k = idx & 63;
        ht[k * 36 + i] = d_h[(size_t)(base + i) * 64 + k];
    }
    __syncthreads();
    int ci = tid & 15, ri = tid >> 4;
    int c0 = ci * 4, n0 = ri * 4;
    float acc[4][4] = {};
#pragma unroll 8
    for (int k = 0; k < 64; k++) {
        const float4 wv = *(const float4*)(Ws + k * 64 + c0);
        const float4 hv = *(const float4*)(ht + k * 36 + n0);
        acc[0][0] += hv.x * wv.x; acc[0][1] += hv.x * wv.y; acc[0][2] += hv.x * wv.z; acc[0][3] += hv.x * wv.w;
        acc[1][0] += hv.y * wv.x; acc[1][1] += hv.y * wv.y; acc[1][2] += hv.y * wv.z; acc[1][3] += hv.y * wv.w;
        acc[2][0] += hv.z * wv.x; acc[2][1] += hv.z * wv.y; acc[2][2] += hv.z * wv.z; acc[2][3] += hv.z * wv.w;
        acc[3][0] += hv.w * wv.x; acc[3][1] += hv.w * wv.y; acc[3][2] += hv.w * wv.z; acc[3][3] += hv.w * wv.w;
    }
    float4 bv = make_float4(bb[c0], bb[c0 + 1], bb[c0 + 2], bb[c0 + 3]);
#pragma unroll
    for (int i = 0; i < 4; i++) {
        float4 o = make_float4(acc[i][0] + bv.x, acc[i][1] + bv.y,
                               acc[i][2] + bv.z, acc[i][3] + bv.w);
        *(float4*)(out + (size_t)(base + n0 + i) * 64 + c0) = o;
    }
}

// ---------------- fused edge aggregation + softmax-normalize + residual + LN ----
// warp per (batch, node). lane j holds dims {2j, 2j+1}; head = j>>3.
__global__ void edge_node_kernel(const float* __restrict__ g,
                                 const float* __restrict__ bta) {
    int w = blockIdx.x * 8 + (threadIdx.x >> 5);   // global warp id, < BN
    int lane = threadIdx.x & 31;
    int n = w % NN;
    int b = w / NN;
    int rowbase = (b * NN + n) * HH;

    const float2 qv = *(const float2*)(d_q + rowbase + 2 * lane);

    int start = d_ptr[n];
    int end = d_ptr[n + 1];

    float accx = 0.0f, accy = 0.0f, den = 0.0f;
    int i = start;
    // unroll by 2 for MLP
    for (; i + 1 < end; i += 2) {
        int s0 = d_csr_src[i];
        int s1 = d_csr_src[i + 1];
        int kb0 = (b * NN + s0) * HH + 2 * lane;
        int kb1 = (b * NN + s1) * HH + 2 * lane;
        float2 k0 = *(const float2*)(d_k + kb0);
        float2 k1 = *(const float2*)(d_k + kb1);
        float2 v0 = *(const float2*)(d_v + kb0);
        float2 v1 = *(const float2*)(d_v + kb1);
        float p0 = qv.x * k0.x + qv.y * k0.y;
        float p1 = qv.x * k1.x + qv.y * k1.y;
        p0 += __shfl_xor_sync(0xFFFFFFFF, p0, 1);
        p1 += __shfl_xor_sync(0xFFFFFFFF, p1, 1);
        p0 += __shfl_xor_sync(0xFFFFFFFF, p0, 2);
        p1 += __shfl_xor_sync(0xFFFFFFFF, p1, 2);
        p0 += __shfl_xor_sync(0xFFFFFFFF, p0, 4);
        p1 += __shfl_xor_sync(0xFFFFFFFF, p1, 4);
        float w0 = __expf(p0 * 0.25f);
        float w1 = __expf(p1 * 0.25f);
        den += w0 + w1;
        accx += w0 * v0.x + w1 * v1.x;
        accy += w0 * v0.y + w1 * v1.y;
    }
    if (i < end) {
        int s0 = d_csr_src[i];
        int kb0 = (b * NN + s0) * HH + 2 * lane;
        float2 k0 = *(const float2*)(d_k + kb0);
        float2 v0 = *(const float2*)(d_v + kb0);
        float p0 = qv.x * k0.x + qv.y * k0.y;
        p0 += __shfl_xor_sync(0xFFFFFFFF, p0, 1);
        p0 += __shfl_xor_sync(0xFFFFFFFF, p0, 2);
        p0 += __shfl_xor_sync(0xFFFFFFFF, p0, 4);
        float w0 = __expf(p0 * 0.25f);
        den += w0;
        accx += w0 * v0.x;
        accy += w0 * v0.y;
    }

    float inv = (den > 0.0f) ? (1.0f / den) : 0.0f;
    const float2 hv = *(const float2*)(d_h + rowbase + 2 * lane);
    const float2 sv = *(const float2*)(d_s + rowbase + 2 * lane);
    float vx = hv.x + accx * inv + sv.x;
    float vy = hv.y + accy * inv + sv.y;

    float sum = vx + vy;
    float sq = vx * vx + vy * vy;
#pragma unroll
    for (int o = 16; o > 0; o >>= 1) {
        sum += __shfl_xor_sync(0xFFFFFFFF, sum, o);
        sq  += __shfl_xor_sync(0xFFFFFFFF, sq, o);
    }
    float mean = sum * (1.0f / 64.0f);
    float var = sq * (1.0f / 64.0f) - mean * mean;
    float rs = rsqrtf(var + EPSF);

    float2 gv = *(const float2*)(g + 2 * lane);
    float2 bv = *(const float2*)(bta + 2 * lane);
    float2 outv;
    outv.x = (vx - mean) * rs * gv.x + bv.x;
    outv.y = (vy - mean) * rs * gv.y + bv.y;
    *(float2*)(d_h + rowbase + 2 * lane) = outv;
}

// ---------------- output projection: out[b,p,n] = h[b,n,:]@out_W + out_b -------
__global__ void out_proj_kernel(const float* __restrict__ oW,
                                const float* __restrict__ ob,
                                float* __restrict__ out) {
    int t = blockIdx.x * blockDim.x + threadIdx.x;
    if (t >= BN) return;
    int b = t / NN, n = t % NN;
    const float4* hr = (const float4*)(d_h + (size_t)t * 64);
    float a0 = ob[0], a1 = ob[1], a2 = ob[2];
#pragma unroll
    for (int i = 0; i < 16; i++) {
        float4 hv = hr[i];
        int h0 = i * 4;
        a0 += hv.x * oW[(h0 + 0) * PP + 0]; a1 += hv.x * oW[(h0 + 0) * PP + 1]; a2 += hv.x * oW[(h0 + 0) * PP + 2];
        a0 += hv.y * oW[(h0 + 1) * PP + 0]; a1 += hv.y * oW[(h0 + 1) * PP + 1]; a2 += hv.y * oW[(h0 + 1) * PP + 2];
        a0 += hv.z * oW[(h0 + 2) * PP + 0]; a1 += hv.z * oW[(h0 + 2) * PP + 1]; a2 += hv.z * oW[(h0 + 2) * PP + 2];
        a0 += hv.w * oW[(h0 + 3) * PP + 0]; a1 += hv.w * oW[(h0 + 3) * PP + 1]; a2 += hv.w * oW[(h0 + 3) * PP + 2];
    }
    out[(size_t)b * PP * NN + 0 * NN + n] = a0;
    out[(size_t)b * PP * NN + 1 * NN + n] = a1;
    out[(size_t)b * PP * NN + 2 * NN + n] = a2;
}

// ---------------- launch --------------------------------------------------------
extern "C" void kernel_launch(void* const* d_in, const int* in_sizes, int n_in,
                              void* d_out, int out_size) {
    const float* x    = (const float*)d_in[0];
    const void*  ei   = d_in[1];
    const float* inW  = (const float*)d_in[2];
    const float* inb  = (const float*)d_in[3];
    const float* Wq   = (const float*)d_in[4];
    const float* bq   = (const float*)d_in[5];
    const float* Wk   = (const float*)d_in[6];
    const float* bk   = (const float*)d_in[7];
    const float* Wv   = (const float*)d_in[8];
    const float* bv   = (const float*)d_in[9];
    const float* Wsk  = (const float*)d_in[10];
    const float* bsk  = (const float*)d_in[11];
    const float* lng  = (const float*)d_in[12];
    const float* lnb  = (const float*)d_in[13];
    const float* oW   = (const float*)d_in[14];
    const float* ob   = (const float*)d_in[15];
    float* out = (float*)d_out;

    detect_kernel<<<1, 1>>>(ei);
    zero_deg_kernel<<<(NN + 255) / 256, 256>>>();
    convert_kernel<<<EE / 256, 256>>>(ei);
    scan_kernel<<<1, 256>>>();
    scatter_kernel<<<EE / 256, 256>>>();

    dim3 ipg((NN + 63) / 64, BB);
    input_proj_kernel<<<ipg, 256>>>(x, inW, inb);

    for (int l = 0; l < LL; l++) {
        const float* wq = Wq + l * HH * HH; const float* bq_ = bq + l * HH;
        const float* wk = Wk + l * HH * HH; const float* bk_ = bk + l * HH;
        const float* wv = Wv + l * HH * HH; const float* bv_ = bv + l * HH;
        const float* ws = Wsk + l * HH * HH; const float* bs_ = bsk + l * HH;

        dim3 gg(BN / 32, 4);
        gemm4_kernel<<<gg, 128>>>(wq, wk, wv, ws, bq_, bk_, bv_, bs_);

        edge_node_kernel<<<BN / 8, 256>>>(lng, lnb);
    }

    out_proj_kernel<<<(BN + 255) / 256, 256>>>(oW, ob, out);
}

// round 3
// speedup vs baseline: 2.0923x; 1.0656x over previous
#include <cuda_runtime.h>
#include <cuda_fp16.h>
#include <math.h>

#define NN 10000
#define EE 320000
#define BB 8
#define SS 12
#define HH 64
#define HEADS 4
#define CC 16
#define LL 3
#define PP 3
#define BN (BB * NN)          // 80000
#define EPSF 1e-5f

// ---------------- scratch (device globals; no allocations allowed) -------------
__device__ __align__(16) float d_h[BN * HH];
__device__ __align__(16) float d_q[BN * HH];
__device__ __align__(16) float d_s[BN * HH];
__device__ __align__(16) __half d_k16[BN * HH];
__device__ __align__(16) __half d_v16[BN * HH];
__device__ int d_src[EE];
__device__ int d_dst[EE];
__device__ int d_deg[NN];
__device__ int d_ptr[NN + 1];
__device__ int d_cnt[NN];
__device__ int d_csr_src[EE];
__device__ int d_is64;

// ---------------- edge index dtype detect ----------------------------------------
__global__ void detect_kernel(const void* ei) {
    const long long* p = (const long long*)ei;
    int is64 = 1;
    for (int i = 0; i < 64; i++) {
        long long v = p[i];
        if (v < 0 || v >= NN) { is64 = 0; break; }
    }
    d_is64 = is64;
}

__global__ void zero_deg_kernel() {
    int i = blockIdx.x * blockDim.x + threadIdx.x;
    if (i < NN) d_deg[i] = 0;
}

// convert + degree histogram
__global__ void convert_kernel(const void* ei) {
    int e = blockIdx.x * blockDim.x + threadIdx.x;
    if (e >= EE) return;
    int s, d;
    if (d_is64) {
        const long long* p = (const long long*)ei;
        s = (int)p[e];
        d = (int)p[EE + e];
    } else {
        const int* p = (const int*)ei;
        s = p[e];
        d = p[EE + e];
    }
    d_src[e] = s;
    d_dst[e] = d;
    atomicAdd(&d_deg[d], 1);
}

// 1024-thread block scan of d_deg -> d_ptr (exclusive) and d_cnt copy
__global__ void scan_kernel() {
    __shared__ int wsums[32];
    int tid = threadIdx.x;               // 1024 threads
    const int PER = 10;                  // 1024*10 >= NN
    int start = tid * PER;
    int degs[PER];
    int local = 0;
#pragma unroll
    for (int i = 0; i < PER; i++) {
        int idx = start + i;
        degs[i] = (idx < NN) ? d_deg[idx] : 0;
        local += degs[i];
    }
    int lane = tid & 31, wid = tid >> 5;
    int scan = local;
#pragma unroll
    for (int o = 1; o < 32; o <<= 1) {
        int t = __shfl_up_sync(0xFFFFFFFF, scan, o);
        if (lane >= o) scan += t;
    }
    if (lane == 31) wsums[wid] = scan;
    __syncthreads();
    if (wid == 0) {
        int v = wsums[lane];
#pragma unroll
        for (int o = 1; o < 32; o <<= 1) {
            int t = __shfl_up_sync(0xFFFFFFFF, v, o);
            if (lane >= o) v += t;
        }
        wsums[lane] = v;
    }
    __syncthreads();
    int excl = scan - local + ((wid > 0) ? wsums[wid - 1] : 0);
#pragma unroll
    for (int i = 0; i < PER; i++) {
        int idx = start + i;
        if (idx < NN) {
            d_ptr[idx] = excl;
            d_cnt[idx] = excl;
            excl += degs[i];
        }
    }
    if (tid == 1023) d_ptr[NN] = EE;
}

// scatter edges into CSR rows by dst
__global__ void scatter_kernel() {
    int e = blockIdx.x * blockDim.x + threadIdx.x;
    if (e >= EE) return;
    int d = d_dst[e];
    int pos = atomicAdd(&d_cnt[d], 1);
    d_csr_src[pos] = d_src[e];
}

// ---------------- input projection: h[b,n,:] = x[b,:,n] @ in_W + in_b ----------
__global__ void input_proj_kernel(const float* __restrict__ x,
                                  const float* __restrict__ inW,
                                  const float* __restrict__ inb) {
    __shared__ float xs[SS * 64];
    __shared__ float Ws[SS * HH];
    int b = blockIdx.y;
    int nb = blockIdx.x * 64;
    int tid = threadIdx.x;   // 256 threads
    for (int idx = tid; idx < SS * HH; idx += 256) Ws[idx] = inW[idx];
    for (int idx = tid; idx < SS * 64; idx += 256) {
        int s = idx >> 6, i = idx & 63;
        int n = nb + i;
        xs[idx] = (n < NN) ? x[(size_t)b * SS * NN + s * NN + n] : 0.0f;
    }
    __syncthreads();
    int j = tid & 63;
    int i0 = (tid >> 6) * 16;
    float bj = inb[j];
    for (int ii = 0; ii < 16; ii++) {
        int i = i0 + ii;
        int n = nb + i;
        if (n >= NN) break;
        float acc = bj;
#pragma unroll
        for (int s = 0; s < SS; s++) acc += xs[s * 64 + i] * Ws[s * HH + j];
        d_h[((size_t)b * NN + n) * HH + j] = acc;
    }
}

// ---------------- QKVS gemm: out = h @ W + b, sel in {q,k,v,skip} --------------
// q,s stored fp32; k,v stored fp16 (read per-edge -> halve L2 traffic)
__global__ void gemm4_kernel(const float* __restrict__ W0, const float* __restrict__ W1,
                             const float* __restrict__ W2, const float* __restrict__ W3,
                             const float* __restrict__ b0, const float* __restrict__ b1,
                             const float* __restrict__ b2, const float* __restrict__ b3) {
    __shared__ float Ws[64 * 64];
    __shared__ float ht[64 * 36];          // padded stride 36 -> float4-aligned rows
    int sel = blockIdx.y;
    const float* W = (sel == 0) ? W0 : (sel == 1) ? W1 : (sel == 2) ? W2 : W3;
    const float* bb = (sel == 0) ? b0 : (sel == 1) ? b1 : (sel == 2) ? b2 : b3;
    int tid = threadIdx.x;   // 128 threads
    int base = blockIdx.x * 32;
    for (int idx = tid; idx < 4096; idx += 128) Ws[idx] = W[idx];
    for (int idx = tid; idx < 2048; idx += 128) {
        int i = idx >> 6, k = idx & 63;
        ht[k * 36 + i] = d_h[(size_t)(base + i) * 64 + k];
    }
    __syncthreads();
    int ci = tid & 15, ri = tid >> 4;
    int c0 = ci * 4, n0 = ri * 4;
    float acc[4][4] = {};
#pragma unroll 8
    for (int k = 0; k < 64; k++) {
        const float4 wv = *(const float4*)(Ws + k * 64 + c0);
        const float4 hv = *(const float4*)(ht + k * 36 + n0);
        acc[0][0] += hv.x * wv.x; acc[0][1] += hv.x * wv.y; acc[0][2] += hv.x * wv.z; acc[0][3] += hv.x * wv.w;
        acc[1][0] += hv.y * wv.x; acc[1][1] += hv.y * wv.y; acc[1][2] += hv.y * wv.z; acc[1][3] += hv.y * wv.w;
        acc[2][0] += hv.z * wv.x; acc[2][1] += hv.z * wv.y; acc[2][2] += hv.z * wv.z; acc[2][3] += hv.z * wv.w;
        acc[3][0] += hv.w * wv.x; acc[3][1] += hv.w * wv.y; acc[3][2] += hv.w * wv.z; acc[3][3] += hv.w * wv.w;
    }
    float4 bv = make_float4(bb[c0], bb[c0 + 1], bb[c0 + 2], bb[c0 + 3]);
    if (sel == 0 || sel == 3) {
        float* out = (sel == 0) ? d_q : d_s;
#pragma unroll
        for (int i = 0; i < 4; i++) {
            float4 o = make_float4(acc[i][0] + bv.x, acc[i][1] + bv.y,
                                   acc[i][2] + bv.z, acc[i][3] + bv.w);
            *(float4*)(out + (size_t)(base + n0 + i) * 64 + c0) = o;
        }
    } else {
        __half* out = (sel == 1) ? d_k16 : d_v16;
#pragma unroll
        for (int i = 0; i < 4; i++) {
            __half2* dst = (__half2*)(out + (size_t)(base + n0 + i) * 64 + c0);
            dst[0] = __floats2half2_rn(acc[i][0] + bv.x, acc[i][1] + bv.y);
            dst[1] = __floats2half2_rn(acc[i][2] + bv.z, acc[i][3] + bv.w);
        }
    }
}

// ---------------- fused edge aggregation + softmax-normalize + residual + LN ----
// warp per (batch, node). lane j holds dims {2j, 2j+1}; head = j>>3.
__global__ void edge_node_kernel(const float* __restrict__ g,
                                 const float* __restrict__ bta) {
    int w = blockIdx.x * 8 + (threadIdx.x >> 5);   // global warp id, < BN
    int lane = threadIdx.x & 31;
    int n = w % NN;
    int b = w / NN;
    int rowbase = (b * NN + n) * HH;

    const float2 qv = *(const float2*)(d_q + rowbase + 2 * lane);
    const __half2* kp = (const __half2*)d_k16;
    const __half2* vp = (const __half2*)d_v16;
    int bbase = b * NN;

    int start = d_ptr[n];
    int end = d_ptr[n + 1];

    float accx = 0.0f, accy = 0.0f, den = 0.0f;
    int i = start;
    for (; i + 3 < end; i += 4) {
        int i0 = (bbase + d_csr_src[i]) * 32 + lane;
        int i1 = (bbase + d_csr_src[i + 1]) * 32 + lane;
        int i2 = (bbase + d_csr_src[i + 2]) * 32 + lane;
        int i3 = (bbase + d_csr_src[i + 3]) * 32 + lane;
        float2 k0 = __half22float2(kp[i0]);
        float2 k1 = __half22float2(kp[i1]);
        float2 k2 = __half22float2(kp[i2]);
        float2 k3 = __half22float2(kp[i3]);
        float2 v0 = __half22float2(vp[i0]);
        float2 v1 = __half22float2(vp[i1]);
        float2 v2 = __half22float2(vp[i2]);
        float2 v3 = __half22float2(vp[i3]);
        float p0 = qv.x * k0.x + qv.y * k0.y;
        float p1 = qv.x * k1.x + qv.y * k1.y;
        float p2 = qv.x * k2.x + qv.y * k2.y;
        float p3 = qv.x * k3.x + qv.y * k3.y;
#pragma unroll
        for (int o = 1; o < 8; o <<= 1) {
            p0 += __shfl_xor_sync(0xFFFFFFFF, p0, o);
            p1 += __shfl_xor_sync(0xFFFFFFFF, p1, o);
            p2 += __shfl_xor_sync(0xFFFFFFFF, p2, o);
            p3 += __shfl_xor_sync(0xFFFFFFFF, p3, o);
        }
        float w0 = __expf(p0 * 0.25f);
        float w1 = __expf(p1 * 0.25f);
        float w2 = __expf(p2 * 0.25f);
        float w3 = __expf(p3 * 0.25f);
        den += (w0 + w1) + (w2 + w3);
        accx += w0 * v0.x + w1 * v1.x + w2 * v2.x + w3 * v3.x;
        accy += w0 * v0.y + w1 * v1.y + w2 * v2.y + w3 * v3.y;
    }
    for (; i < end; i++) {
        int i0 = (bbase + d_csr_src[i]) * 32 + lane;
        float2 k0 = __half22float2(kp[i0]);
        float2 v0 = __half22float2(vp[i0]);
        float p0 = qv.x * k0.x + qv.y * k0.y;
#pragma unroll
        for (int o = 1; o < 8; o <<= 1)
            p0 += __shfl_xor_sync(0xFFFFFFFF, p0, o);
        float w0 = __expf(p0 * 0.25f);
        den += w0;
        accx += w0 * v0.x;
        accy += w0 * v0.y;
    }

    float inv = (den > 0.0f) ? (1.0f / den) : 0.0f;
    const float2 hv = *(const float2*)(d_h + rowbase + 2 * lane);
    const float2 sv = *(const float2*)(d_s + rowbase + 2 * lane);
    float vx = hv.x + accx * inv + sv.x;
    float vy = hv.y + accy * inv + sv.y;

    float sum = vx + vy;
    float sq = vx * vx + vy * vy;
#pragma unroll
    for (int o = 16; o > 0; o >>= 1) {
        sum += __shfl_xor_sync(0xFFFFFFFF, sum, o);
        sq  += __shfl_xor_sync(0xFFFFFFFF, sq, o);
    }
    float mean = sum * (1.0f / 64.0f);
    float var = sq * (1.0f / 64.0f) - mean * mean;
    float rs = rsqrtf(var + EPSF);

    float2 gv = *(const float2*)(g + 2 * lane);
    float2 bv = *(const float2*)(bta + 2 * lane);
    float2 outv;
    outv.x = (vx - mean) * rs * gv.x + bv.x;
    outv.y = (vy - mean) * rs * gv.y + bv.y;
    *(float2*)(d_h + rowbase + 2 * lane) = outv;
}

// ---------------- output projection: out[b,p,n] = h[b,n,:]@out_W + out_b -------
__global__ void out_proj_kernel(const float* __restrict__ oW,
                                const float* __restrict__ ob,
                                float* __restrict__ out) {
    int t = blockIdx.x * blockDim.x + threadIdx.x;
    if (t >= BN) return;
    int b = t / NN, n = t % NN;
    const float4* hr = (const float4*)(d_h + (size_t)t * 64);
    float a0 = ob[0], a1 = ob[1], a2 = ob[2];
#pragma unroll
    for (int i = 0; i < 16; i++) {
        float4 hv = hr[i];
        int h0 = i * 4;
        a0 += hv.x * oW[(h0 + 0) * PP + 0]; a1 += hv.x * oW[(h0 + 0) * PP + 1]; a2 += hv.x * oW[(h0 + 0) * PP + 2];
        a0 += hv.y * oW[(h0 + 1) * PP + 0]; a1 += hv.y * oW[(h0 + 1) * PP + 1]; a2 += hv.y * oW[(h0 + 1) * PP + 2];
        a0 += hv.z * oW[(h0 + 2) * PP + 0]; a1 += hv.z * oW[(h0 + 2) * PP + 1]; a2 += hv.z * oW[(h0 + 2) * PP + 2];
        a0 += hv.w * oW[(h0 + 3) * PP + 0]; a1 += hv.w * oW[(h0 + 3) * PP + 1]; a2 += hv.w * oW[(h0 + 3) * PP + 2];
    }
    out[(size_t)b * PP * NN + 0 * NN + n] = a0;
    out[(size_t)b * PP * NN + 1 * NN + n] = a1;
    out[(size_t)b * PP * NN + 2 * NN + n] = a2;
}

// ---------------- launch --------------------------------------------------------
extern "C" void kernel_launch(void* const* d_in, const int* in_sizes, int n_in,
                              void* d_out, int out_size) {
    const float* x    = (const float*)d_in[0];
    const void*  ei   = d_in[1];
    const float* inW  = (const float*)d_in[2];
    const float* inb  = (const float*)d_in[3];
    const float* Wq   = (const float*)d_in[4];
    const float* bq   = (const float*)d_in[5];
    const float* Wk   = (const float*)d_in[6];
    const float* bk   = (const float*)d_in[7];
    const float* Wv   = (const float*)d_in[8];
    const float* bv   = (const float*)d_in[9];
    const float* Wsk  = (const float*)d_in[10];
    const float* bsk  = (const float*)d_in[11];
    const float* lng  = (const float*)d_in[12];
    const float* lnb  = (const float*)d_in[13];
    const float* oW   = (const float*)d_in[14];
    const float* ob   = (const float*)d_in[15];
    float* out = (float*)d_out;

    detect_kernel<<<1, 1>>>(ei);
    zero_deg_kernel<<<(NN + 255) / 256, 256>>>();
    convert_kernel<<<EE / 256, 256>>>(ei);
    scan_kernel<<<1, 1024>>>();
    scatter_kernel<<<EE / 256, 256>>>();

    dim3 ipg((NN + 63) / 64, BB);
    input_proj_kernel<<<ipg, 256>>>(x, inW, inb);

    for (int l = 0; l < LL; l++) {
        const float* wq = Wq + l * HH * HH; const float* bq_ = bq + l * HH;
        const float* wk = Wk + l * HH * HH; const float* bk_ = bk + l * HH;
        const float* wv = Wv + l * HH * HH; const float* bv_ = bv + l * HH;
        const float* ws = Wsk + l * HH * HH; const float* bs_ = bsk + l * HH;

        dim3 gg(BN / 32, 4);
        gemm4_kernel<<<gg, 128>>>(wq, wk, wv, ws, bq_, bk_, bv_, bs_);

        edge_node_kernel<<<BN / 8, 256>>>(lng, lnb);
    }

    out_proj_kernel<<<(BN + 255) / 256, 256>>>(oW, ob, out);
}

// round 7
// speedup vs baseline: 2.4098x; 1.1517x over previous
#include <cuda_runtime.h>
#include <cuda_fp16.h>
#include <mma.h>
#include <math.h>

using namespace nvcuda;

#define NN 10000
#define EE 320000
#define BB 8
#define SS 12
#define HH 64
#define HEADS 4
#define CC 16
#define LL 3
#define PP 3
#define BN (BB * NN)
#define EPSF 1e-5f

__device__ __align__(16) float d_h[BN * HH];
__device__ __align__(16) __half d_h16[BN * HH];
__device__ __align__(16) float d_q[BN * HH];
__device__ __align__(16) float d_s[BN * HH];
__device__ __align__(16) __half d_k16[BN * HH];
__device__ __align__(16) __half d_v16[BN * HH];
__device__ __align__(16) __half d_W16all[LL * 4 * HH * HH];
__device__ int d_src[EE];
__device__ int d_dst[EE];
__device__ int d_deg[NN];
__device__ int d_ptr[NN + 1];
__device__ int d_cnt[NN];
__device__ int d_csr_src[EE];
__device__ int d_is64;

__global__ void detect_kernel(const void* ei) {
    const long long* p = (const long long*)ei;
    int is64 = 1;
    for (int i = 0; i < 64; i++) {
        long long v = p[i];
        if (v < 0 || v >= NN) { is64 = 0; break; }
    }
    d_is64 = is64;
}

__global__ void zero_deg_kernel() {
    int i = blockIdx.x * blockDim.x + threadIdx.x;
    if (i < NN) d_deg[i] = 0;
}

__global__ void convert_kernel(const void* ei) {
    int e = blockIdx.x * blockDim.x + threadIdx.x;
    if (e >= EE) return;
    int s, d;
    if (d_is64) {
        const long long* p = (const long long*)ei;
        s = (int)p[e];
        d = (int)p[EE + e];
    } else {
        const int* p = (const int*)ei;
        s = p[e];
        d = p[EE + e];
    }
    d_src[e] = s;
    d_dst[e] = d;
    atomicAdd(&d_deg[d], 1);
}

__global__ void scan_kernel() {
    __shared__ int wsums[32];
    int tid = threadIdx.x;
    const int PER = 10;
    int start = tid * PER;
    int degs[PER];
    int local = 0;
#pragma unroll
    for (int i = 0; i < PER; i++) {
        int idx = start + i;
        degs[i] = (idx < NN) ? d_deg[idx] : 0;
        local += degs[i];
    }
    int lane = tid & 31, wid = tid >> 5;
    int scan = local;
#pragma unroll
    for (int o = 1; o < 32; o <<= 1) {
        int t = __shfl_up_sync(0xFFFFFFFF, scan, o);
        if (lane >= o) scan += t;
    }
    if (lane == 31) wsums[wid] = scan;
    __syncthreads();
    if (wid == 0) {
        int v = wsums[lane];
#pragma unroll
        for (int o = 1; o < 32; o <<= 1) {
            int t = __shfl_up_sync(0xFFFFFFFF, v, o);
            if (lane >= o) v += t;
        }
        wsums[lane] = v;
    }
    __syncthreads();
    int excl = scan - local + ((wid > 0) ? wsums[wid - 1] : 0);
#pragma unroll
    for (int i = 0; i < PER; i++) {
        int idx = start + i;
        if (idx < NN) {
            d_ptr[idx] = excl;
            d_cnt[idx] = excl;
            excl += degs[i];
        }
    }
    if (tid == 1023) d_ptr[NN] = EE;
}

__global__ void scatter_kernel() {
    int e = blockIdx.x * blockDim.x + threadIdx.x;
    if (e >= EE) return;
    int d = d_dst[e];
    int pos = atomicAdd(&d_cnt[d], 1);
    d_csr_src[pos] = d_src[e];
}

__global__ void convw_kernel(const float* __restrict__ Wq, const float* __restrict__ Wk,
                             const float* __restrict__ Wv, const float* __restrict__ Wsk) {
    int idx = blockIdx.x * blockDim.x + threadIdx.x;
    if (idx >= LL * 4 * 4096) return;
    int l = idx >> 14;
    int sel = (idx >> 12) & 3;
    int j = idx & 4095;
    const float* W = (sel == 0) ? Wq : (sel == 1) ? Wk : (sel == 2) ? Wv : Wsk;
    d_W16all[idx] = __float2half(W[l * 4096 + j]);
}

__global__ void input_proj_kernel(const float* __restrict__ x,
                                  const float* __restrict__ inW,
                                  const float* __restrict__ inb) {
    __shared__ float xs[SS * 64];
    __shared__ float Ws[SS * HH];
    int b = blockIdx.y;
    int nb = blockIdx.x * 64;
    int tid = threadIdx.x;
    for (int idx = tid; idx < SS * HH; idx += 256) Ws[idx] = inW[idx];
    for (int idx = tid; idx < SS * 64; idx += 256) {
        int s = idx >> 6, i = idx & 63;
        int n = nb + i;
        xs[idx] = (n < NN) ? x[(size_t)b * SS * NN + s * NN + n] : 0.0f;
    }
    __syncthreads();
    int j = tid & 63;
    int i0 = (tid >> 6) * 16;
    float bj = inb[j];
    for (int ii = 0; ii < 16; ii++) {
        int i = i0 + ii;
        int n = nb + i;
        if (n >= NN) break;
        float acc = bj;
#pragma unroll
        for (int s = 0; s < SS; s++) acc += xs[s * 64 + i] * Ws[s * HH + j];
        size_t o = ((size_t)b * NN + n) * HH + j;
        d_h[o] = acc;
        d_h16[o] = __float2half(acc);
    }
}

// 512 threads = 16 warps: warp = rowtile(0-3) + 4*sel(0-3). 64 rows per block.
__global__ void gemm_wmma_kernel(int layer,
                                 const float* __restrict__ b0, const float* __restrict__ b1,
                                 const float* __restrict__ b2, const float* __restrict__ b3) {
    __shared__ float stage[16][256];
    int warp = threadIdx.x >> 5;
    int lane = threadIdx.x & 31;
    int rt = warp & 3;
    int wsel = warp >> 2;
    int base = blockIdx.x * 64 + rt * 16;
    const __half* A = d_h16 + (size_t)base * 64;
    const __half* B = d_W16all + ((size_t)layer * 4 + wsel) * 4096;

    wmma::fragment<wmma::accumulator, 16, 16, 16, float> acc[4];
#pragma unroll
    for (int nt = 0; nt < 4; nt++) wmma::fill_fragment(acc[nt], 0.0f);

#pragma unroll
    for (int kk = 0; kk < 4; kk++) {
        wmma::fragment<wmma::matrix_a, 16, 16, 16, __half, wmma::row_major> a;
        wmma::load_matrix_sync(a, A + kk * 16, 64);
#pragma unroll
        for (int nt = 0; nt < 4; nt++) {
            wmma::fragment<wmma::matrix_b, 16, 16, 16, __half, wmma::row_major> b;
            wmma::load_matrix_sync(b, B + (size_t)kk * 16 * 64 + nt * 16, 64);
            wmma::mma_sync(acc[nt], a, b, acc[nt]);
        }
    }

    const float* bias = (wsel == 0) ? b0 : (wsel == 1) ? b1 : (wsel == 2) ? b2 : b3;
    float* stg = &stage[warp][0];
    int r = lane >> 1, c0 = (lane & 1) * 8;
#pragma unroll
    for (int nt = 0; nt < 4; nt++) {
        wmma::store_matrix_sync(stg, acc[nt], 16, wmma::mem_row_major);
        __syncwarp();
        int gr = base + r;
        int gc = nt * 16 + c0;
        float vals[8];
#pragma unroll
        for (int t = 0; t < 8; t++) vals[t] = stg[r * 16 + c0 + t] + bias[gc + t];
        if (wsel == 0 || wsel == 3) {
            float* outp = (wsel == 0) ? d_q : d_s;
            *(float4*)(outp + (size_t)gr * 64 + gc) = make_float4(vals[0], vals[1], vals[2], vals[3]);
            *(float4*)(outp + (size_t)gr * 64 + gc + 4) = make_float4(vals[4], vals[5], vals[6], vals[7]);
        } else {
            __half* outp = (wsel == 1) ? d_k16 : d_v16;
            __half2 h2[4];
#pragma unroll
            for (int t = 0; t < 4; t++) h2[t] = __floats2half2_rn(vals[2 * t], vals[2 * t + 1]);
            *(uint4*)(outp + (size_t)gr * 64 + gc) = *(uint4*)h2;
        }
        __syncwarp();
    }
}

// warp per (batch, node); two 16-lane halves each process one edge; lane covers
// 4 dims; dot-reduce over 4 lanes (shfl 1,2); cross-half combine at end.
__global__ void edge_node_kernel(const float* __restrict__ g,
                                 const float* __restrict__ bta) {
    int w = blockIdx.x * 8 + (threadIdx.x >> 5);
    int lane = threadIdx.x & 31;
    int half = lane >> 4;
    int sub = lane & 15;
    int n = w % NN;
    int b = w / NN;
    int rowbase = (b * NN + n) * HH;
    int bbase = b * NN;

    const float4 qv = *(const float4*)(d_q + rowbase + sub * 4);

    int start = d_ptr[n];
    int end = d_ptr[n + 1];

    float4 acc = make_float4(0.f, 0.f, 0.f, 0.f);
    float den = 0.0f;

    int i = start;
    for (; i + 3 < end; i += 4) {
        int s0 = d_csr_src[i + half];
        int s1 = d_csr_src[i + 2 + half];
        const __half* kr0 = d_k16 + (size_t)(bbase + s0) * 64 + sub * 4;
        const __half* kr1 = d_k16 + (size_t)(bbase + s1) * 64 + sub * 4;
        const __half* vr0 = d_v16 + (size_t)(bbase + s0) * 64 + sub * 4;
        const __half* vr1 = d_v16 + (size_t)(bbase + s1) * 64 + sub * 4;
        uint2 ku0 = *(const uint2*)kr0;
        uint2 ku1 = *(const uint2*)kr1;
        uint2 vu0 = *(const uint2*)vr0;
        uint2 vu1 = *(const uint2*)vr1;
        float2 k0a = __half22float2(*(__half2*)&ku0.x), k0b = __half22float2(*(__half2*)&ku0.y);
        float2 k1a = __half22float2(*(__half2*)&ku1.x), k1b = __half22float2(*(__half2*)&ku1.y);
        float p0 = qv.x * k0a.x + qv.y * k0a.y + qv.z * k0b.x + qv.w * k0b.y;
        float p1 = qv.x * k1a.x + qv.y * k1a.y + qv.z * k1b.x + qv.w * k1b.y;
        p0 += __shfl_xor_sync(0xFFFFFFFF, p0, 1);
        p1 += __shfl_xor_sync(0xFFFFFFFF, p1, 1);
        p0 += __shfl_xor_sync(0xFFFFFFFF, p0, 2);
        p1 += __shfl_xor_sync(0xFFFFFFFF, p1, 2);
        float w0 = __expf(p0 * 0.25f);
        float w1 = __expf(p1 * 0.25f);
        float2 v0a = __half22float2(*(__half2*)&vu0.x), v0b = __half22float2(*(__half2*)&vu0.y);
        float2 v1a = __half22float2(*(__half2*)&vu1.x), v1b = __half22float2(*(__half2*)&vu1.y);
        den += w0 + w1;
        acc.x += w0 * v0a.x + w1 * v1a.x;
        acc.y += w0 * v0a.y + w1 * v1a.y;
        acc.z += w0 * v0b.x + w1 * v1b.x;
        acc.w += w0 * v0b.y + w1 * v1b.y;
    }
    for (; i < end; i += 2) {
        int e0 = i + half;
        bool valid = (e0 < end);
        int s0 = d_csr_src[valid ? e0 : i];
        const __half* kr0 = d_k16 + (size_t)(bbase + s0) * 64 + sub * 4;
        const __half* vr0 = d_v16 + (size_t)(bbase + s0) * 64 + sub * 4;
        uint2 ku0 = *(const uint2*)kr0;
        uint2 vu0 = *(const uint2*)vr0;
        float2 k0a = __half22float2(*(__half2*)&ku0.x), k0b = __half22float2(*(__half2*)&ku0.y);
        float p0 = qv.x * k0a.x + qv.y * k0a.y + qv.z * k0b.x + qv.w * k0b.y;
        p0 += __shfl_xor_sync(0xFFFFFFFF, p0, 1);
        p0 += __shfl_xor_sync(0xFFFFFFFF, p0, 2);
        float w0 = valid ? __expf(p0 * 0.25f) : 0.0f;
        float2 v0a = __half22float2(*(__half2*)&vu0.x), v0b = __half22float2(*(__half2*)&vu0.y);
        den += w0;
        acc.x += w0 * v0a.x;
        acc.y += w0 * v0a.y;
        acc.z += w0 * v0b.x;
        acc.w += w0 * v0b.y;
    }

    acc.x += __shfl_xor_sync(0xFFFFFFFF, acc.x, 16);
    acc.y += __shfl_xor_sync(0xFFFFFFFF, acc.y, 16);
    acc.z += __shfl_xor_sync(0xFFFFFFFF, acc.z, 16);
    acc.w += __shfl_xor_sync(0xFFFFFFFF, acc.w, 16);
    den += __shfl_xor_sync(0xFFFFFFFF, den, 16);

    float inv = (den > 0.0f) ? (1.0f / den) : 0.0f;
    const float4 hv = *(const float4*)(d_h + rowbase + sub * 4);
    const float4 sv = *(const float4*)(d_s + rowbase + sub * 4);
    float4 val;
    val.x = hv.x + acc.x * inv + sv.x;
    val.y = hv.y + acc.y * inv + sv.y;
    val.z = hv.z + acc.z * inv + sv.z;
    val.w = hv.w + acc.w * inv + sv.w;

    float sum = val.x + val.y + val.z + val.w;
    float sq = val.x * val.x + val.y * val.y + val.z * val.z + val.w * val.w;
#pragma unroll
    for (int o = 16; o > 0; o >>= 1) {
        sum += __shfl_xor_sync(0xFFFFFFFF, sum, o);
        sq  += __shfl_xor_sync(0xFFFFFFFF, sq, o);
    }
    float mean = sum * (1.0f / 128.0f);
    float var = sq * (1.0f / 128.0f) - mean * mean;
    float rs = rsqrtf(var + EPSF);

    const float4 gv = *(const float4*)(g + sub * 4);
    const float4 bv = *(const float4*)(bta + sub * 4);
    float4 outv;
    outv.x = (val.x - mean) * rs * gv.x + bv.x;
    outv.y = (val.y - mean) * rs * gv.y + bv.y;
    outv.z = (val.z - mean) * rs * gv.z + bv.z;
    outv.w = (val.w - mean) * rs * gv.w + bv.w;

    if (half == 0) {
        *(float4*)(d_h + rowbase + sub * 4) = outv;
        __half2 h2[2];
        h2[0] = __floats2half2_rn(outv.x, outv.y);
        h2[1] = __floats2half2_rn(outv.z, outv.w);
        *(uint2*)(d_h16 + rowbase + sub * 4) = *(uint2*)h2;
    }
}

__global__ void out_proj_kernel(const float* __restrict__ oW,
                                const float* __restrict__ ob,
                                float* __restrict__ out) {
    int t = blockIdx.x * blockDim.x + threadIdx.x;
    if (t >= BN) return;
    int b = t / NN, n = t % NN;
    const float4* hr = (const float4*)(d_h + (size_t)t * 64);
    float a0 = ob[0], a1 = ob[1], a2 = ob[2];
#pragma unroll
    for (int i = 0; i < 16; i++) {
        float4 hv = hr[i];
        int h0 = i * 4;
        a0 += hv.x * oW[(h0 + 0) * PP + 0]; a1 += hv.x * oW[(h0 + 0) * PP + 1]; a2 += hv.x * oW[(h0 + 0) * PP + 2];
        a0 += hv.y * oW[(h0 + 1) * PP + 0]; a1 += hv.y * oW[(h0 + 1) * PP + 1]; a2 += hv.y * oW[(h0 + 1) * PP + 2];
        a0 += hv.z * oW[(h0 + 2) * PP + 0]; a1 += hv.z * oW[(h0 + 2) * PP + 1]; a2 += hv.z * oW[(h0 + 2) * PP + 2];
        a0 += hv.w * oW[(h0 + 3) * PP + 0]; a1 += hv.w * oW[(h0 + 3) * PP + 1]; a2 += hv.w * oW[(h0 + 3) * PP + 2];
    }
    out[(size_t)b * PP * NN + 0 * NN + n] = a0;
    out[(size_t)b * PP * NN + 1 * NN + n] = a1;
    out[(size_t)b * PP * NN + 2 * NN + n] = a2;
}

extern "C" void kernel_launch(void* const* d_in, const int* in_sizes, int n_in,
                              void* d_out, int out_size) {
    const float* x    = (const float*)d_in[0];
    const void*  ei   = d_in[1];
    const float* inW  = (const float*)d_in[2];
    const float* inb  = (const float*)d_in[3];
    const float* Wq   = (const float*)d_in[4];
    const float* bq   = (const float*)d_in[5];
    const float* Wk   = (const float*)d_in[6];
    const float* bk   = (const float*)d_in[7];
    const float* Wv   = (const float*)d_in[8];
    const float* bv   = (const float*)d_in[9];
    const float* Wsk  = (const float*)d_in[10];
    const float* bsk  = (const float*)d_in[11];
    const float* lng  = (const float*)d_in[12];
    const float* lnb  = (const float*)d_in[13];
    const float* oW   = (const float*)d_in[14];
    const float* ob   = (const float*)d_in[15];
    float* out = (float*)d_out;

    detect_kernel<<<1, 1>>>(ei);
    zero_deg_kernel<<<(NN + 255) / 256, 256>>>();
    convert_kernel<<<EE / 256, 256>>>(ei);
    scan_kernel<<<1, 1024>>>();
    scatter_kernel<<<EE / 256, 256>>>();
    convw_kernel<<<(LL * 4 * 4096 + 255) / 256, 256>>>(Wq, Wk, Wv, Wsk);

    dim3 ipg((NN + 63) / 64, BB);
    input_proj_kernel<<<ipg, 256>>>(x, inW, inb);

    for (int l = 0; l < LL; l++) {
        gemm_wmma_kernel<<<BN / 64, 512>>>(l, bq + l * HH, bk + l * HH,
                                           bv + l * HH, bsk + l * HH);
        edge_node_kernel<<<BN / 8, 256>>>(lng, lnb);
    }

    out_proj_kernel<<<(BN + 255) / 256, 256>>>(oW, ob, out);
}

// round 8
// speedup vs baseline: 2.4857x; 1.0315x over previous
#include <cuda_runtime.h>
#include <cuda_fp16.h>
#include <mma.h>
#include <math.h>

using namespace nvcuda;

#define NN 10000
#define EE 320000
#define BB 8
#define SS 12
#define HH 64
#define HEADS 4
#define CC 16
#define LL 3
#define PP 3
#define BN (BB * NN)
#define EPSF 1e-5f

__device__ __align__(16) float d_h[BN * HH];
__device__ __align__(16) __half d_h16[BN * HH];
__device__ __align__(16) float d_q[BN * HH];
__device__ __align__(16) float d_s[BN * HH];
__device__ __align__(16) __half d_k16[BN * HH];
__device__ __align__(16) __half d_v16[BN * HH];
__device__ __align__(16) __half d_W16all[LL * 4 * HH * HH];
__device__ int d_src[EE];
__device__ int d_dst[EE];
__device__ int d_deg[NN];
__device__ int d_ptr[NN + 1];
__device__ int d_cnt[NN];
__device__ int d_csr_src[EE];
__device__ int d_is64;

__global__ void detect_kernel(const void* ei) {
    const long long* p = (const long long*)ei;
    int is64 = 1;
    for (int i = 0; i < 64; i++) {
        long long v = p[i];
        if (v < 0 || v >= NN) { is64 = 0; break; }
    }
    d_is64 = is64;
}

__global__ void zero_deg_kernel() {
    int i = blockIdx.x * blockDim.x + threadIdx.x;
    if (i < NN) d_deg[i] = 0;
}

__global__ void convert_kernel(const void* ei) {
    int e = blockIdx.x * blockDim.x + threadIdx.x;
    if (e >= EE) return;
    int s, d;
    if (d_is64) {
        const long long* p = (const long long*)ei;
        s = (int)p[e];
        d = (int)p[EE + e];
    } else {
        const int* p = (const int*)ei;
        s = p[e];
        d = p[EE + e];
    }
    d_src[e] = s;
    d_dst[e] = d;
    atomicAdd(&d_deg[d], 1);
}

__global__ void scan_kernel() {
    __shared__ int wsums[32];
    int tid = threadIdx.x;
    const int PER = 10;
    int start = tid * PER;
    int degs[PER];
    int local = 0;
#pragma unroll
    for (int i = 0; i < PER; i++) {
        int idx = start + i;
        degs[i] = (idx < NN) ? d_deg[idx] : 0;
        local += degs[i];
    }
    int lane = tid & 31, wid = tid >> 5;
    int scan = local;
#pragma unroll
    for (int o = 1; o < 32; o <<= 1) {
        int t = __shfl_up_sync(0xFFFFFFFF, scan, o);
        if (lane >= o) scan += t;
    }
    if (lane == 31) wsums[wid] = scan;
    __syncthreads();
    if (wid == 0) {
        int v = wsums[lane];
#pragma unroll
        for (int o = 1; o < 32; o <<= 1) {
            int t = __shfl_up_sync(0xFFFFFFFF, v, o);
            if (lane >= o) v += t;
        }
        wsums[lane] = v;
    }
    __syncthreads();
    int excl = scan - local + ((wid > 0) ? wsums[wid - 1] : 0);
#pragma unroll
    for (int i = 0; i < PER; i++) {
        int idx = start + i;
        if (idx < NN) {
            d_ptr[idx] = excl;
            d_cnt[idx] = excl;
            excl += degs[i];
        }
    }
    if (tid == 1023) d_ptr[NN] = EE;
}

__global__ void scatter_kernel() {
    int e = blockIdx.x * blockDim.x + threadIdx.x;
    if (e >= EE) return;
    int d = d_dst[e];
    int pos = atomicAdd(&d_cnt[d], 1);
    d_csr_src[pos] = d_src[e];
}

__global__ void convw_kernel(const float* __restrict__ Wq, const float* __restrict__ Wk,
                             const float* __restrict__ Wv, const float* __restrict__ Wsk) {
    int idx = blockIdx.x * blockDim.x + threadIdx.x;
    if (idx >= LL * 4 * 4096) return;
    int l = idx >> 14;
    int sel = (idx >> 12) & 3;
    int j = idx & 4095;
    const float* W = (sel == 0) ? Wq : (sel == 1) ? Wk : (sel == 2) ? Wv : Wsk;
    d_W16all[idx] = __float2half(W[l * 4096 + j]);
}

__global__ void input_proj_kernel(const float* __restrict__ x,
                                  const float* __restrict__ inW,
                                  const float* __restrict__ inb) {
    __shared__ float xs[SS * 64];
    __shared__ float Ws[SS * HH];
    int b = blockIdx.y;
    int nb = blockIdx.x * 64;
    int tid = threadIdx.x;
    for (int idx = tid; idx < SS * HH; idx += 256) Ws[idx] = inW[idx];
    for (int idx = tid; idx < SS * 64; idx += 256) {
        int s = idx >> 6, i = idx & 63;
        int n = nb + i;
        xs[idx] = (n < NN) ? x[(size_t)b * SS * NN + s * NN + n] : 0.0f;
    }
    __syncthreads();
    int j = tid & 63;
    int i0 = (tid >> 6) * 16;
    float bj = inb[j];
    for (int ii = 0; ii < 16; ii++) {
        int i = i0 + ii;
        int n = nb + i;
        if (n >= NN) break;
        float acc = bj;
#pragma unroll
        for (int s = 0; s < SS; s++) acc += xs[s * 64 + i] * Ws[s * HH + j];
        size_t o = ((size_t)b * NN + n) * HH + j;
        d_h[o] = acc;
        d_h16[o] = __float2half(acc);
    }
}

// 512 threads = 16 warps: warp = rowtile(0-3) + 4*sel(0-3). 64 rows per block.
__global__ void gemm_wmma_kernel(int layer,
                                 const float* __restrict__ b0, const float* __restrict__ b1,
                                 const float* __restrict__ b2, const float* __restrict__ b3) {
    __shared__ float stage[16][256];
    int warp = threadIdx.x >> 5;
    int lane = threadIdx.x & 31;
    int rt = warp & 3;
    int wsel = warp >> 2;
    int base = blockIdx.x * 64 + rt * 16;
    const __half* A = d_h16 + (size_t)base * 64;
    const __half* B = d_W16all + ((size_t)layer * 4 + wsel) * 4096;

    wmma::fragment<wmma::accumulator, 16, 16, 16, float> acc[4];
#pragma unroll
    for (int nt = 0; nt < 4; nt++) wmma::fill_fragment(acc[nt], 0.0f);

#pragma unroll
    for (int kk = 0; kk < 4; kk++) {
        wmma::fragment<wmma::matrix_a, 16, 16, 16, __half, wmma::row_major> a;
        wmma::load_matrix_sync(a, A + kk * 16, 64);
#pragma unroll
        for (int nt = 0; nt < 4; nt++) {
            wmma::fragment<wmma::matrix_b, 16, 16, 16, __half, wmma::row_major> b;
            wmma::load_matrix_sync(b, B + (size_t)kk * 16 * 64 + nt * 16, 64);
            wmma::mma_sync(acc[nt], a, b, acc[nt]);
        }
    }

    const float* bias = (wsel == 0) ? b0 : (wsel == 1) ? b1 : (wsel == 2) ? b2 : b3;
    float* stg = &stage[warp][0];
    int r = lane >> 1, c0 = (lane & 1) * 8;
#pragma unroll
    for (int nt = 0; nt < 4; nt++) {
        wmma::store_matrix_sync(stg, acc[nt], 16, wmma::mem_row_major);
        __syncwarp();
        int gr = base + r;
        int gc = nt * 16 + c0;
        float vals[8];
#pragma unroll
        for (int t = 0; t < 8; t++) vals[t] = stg[r * 16 + c0 + t] + bias[gc + t];
        if (wsel == 0 || wsel == 3) {
            float* outp = (wsel == 0) ? d_q : d_s;
            *(float4*)(outp + (size_t)gr * 64 + gc) = make_float4(vals[0], vals[1], vals[2], vals[3]);
            *(float4*)(outp + (size_t)gr * 64 + gc + 4) = make_float4(vals[4], vals[5], vals[6], vals[7]);
        } else {
            __half* outp = (wsel == 1) ? d_k16 : d_v16;
            __half2 h2[4];
#pragma unroll
            for (int t = 0; t < 4; t++) h2[t] = __floats2half2_rn(vals[2 * t], vals[2 * t + 1]);
            *(uint4*)(outp + (size_t)gr * 64 + gc) = *(uint4*)h2;
        }
        __syncwarp();
    }
}

// warp per (batch, node); lane = (quarter: edge slot 0-3, sub: dim group 0-7).
// Each lane owns 8 dims = half a head, so the per-head 16-dim dot needs ONE
// shfl (xor 1). k/v loaded as uint4 (LDG.128). 4 edges per iteration,
// predicated tail. Quarter-combine via shfl xor 8,16.
__global__ void edge_node_kernel(const float* __restrict__ g,
                                 const float* __restrict__ bta) {
    int w = blockIdx.x * 8 + (threadIdx.x >> 5);
    int lane = threadIdx.x & 31;
    int quarter = lane >> 3;
    int sub = lane & 7;
    int n = w % NN;
    int b = w / NN;
    int rowbase = (b * NN + n) * HH;
    int bbase = b * NN;

    const float4 qa = *(const float4*)(d_q + rowbase + sub * 8);
    const float4 qb = *(const float4*)(d_q + rowbase + sub * 8 + 4);

    int start = d_ptr[n];
    int end = d_ptr[n + 1];

    const uint4* kp = (const uint4*)d_k16;   // one k row = 8 uint4
    const uint4* vp = (const uint4*)d_v16;

    float acc0 = 0.f, acc1 = 0.f, acc2 = 0.f, acc3 = 0.f;
    float acc4 = 0.f, acc5 = 0.f, acc6 = 0.f, acc7 = 0.f;
    float den = 0.f;

    for (int i = start; i < end; i += 4) {
        int e = i + quarter;
        bool valid = (e < end);
        int s = d_csr_src[valid ? e : (end - 1)];
        size_t ro = (size_t)(bbase + s) * 8 + sub;
        uint4 ku = kp[ro];
        uint4 vu = vp[ro];
        float2 k0 = __half22float2(*(__half2*)&ku.x);
        float2 k1 = __half22float2(*(__half2*)&ku.y);
        float2 k2 = __half22float2(*(__half2*)&ku.z);
        float2 k3 = __half22float2(*(__half2*)&ku.w);
        float p = qa.x * k0.x + qa.y * k0.y + qa.z * k1.x + qa.w * k1.y
                + qb.x * k2.x + qb.y * k2.y + qb.z * k3.x + qb.w * k3.y;
        p += __shfl_xor_sync(0xFFFFFFFF, p, 1);   // 16-dim head dot
        float wt = valid ? __expf(p * 0.25f) : 0.f;
        den += wt;
        float2 v0 = __half22float2(*(__half2*)&vu.x);
        float2 v1 = __half22float2(*(__half2*)&vu.y);
        float2 v2 = __half22float2(*(__half2*)&vu.z);
        float2 v3 = __half22float2(*(__half2*)&vu.w);
        acc0 += wt * v0.x; acc1 += wt * v0.y;
        acc2 += wt * v1.x; acc3 += wt * v1.y;
        acc4 += wt * v2.x; acc5 += wt * v2.y;
        acc6 += wt * v3.x; acc7 += wt * v3.y;
    }

    // combine the 4 edge-quarters (lanes with same sub, different quarter)
#pragma unroll
    for (int o = 8; o <= 16; o <<= 1) {
        acc0 += __shfl_xor_sync(0xFFFFFFFF, acc0, o);
        acc1 += __shfl_xor_sync(0xFFFFFFFF, acc1, o);
        acc2 += __shfl_xor_sync(0xFFFFFFFF, acc2, o);
        acc3 += __shfl_xor_sync(0xFFFFFFFF, acc3, o);
        acc4 += __shfl_xor_sync(0xFFFFFFFF, acc4, o);
        acc5 += __shfl_xor_sync(0xFFFFFFFF, acc5, o);
        acc6 += __shfl_xor_sync(0xFFFFFFFF, acc6, o);
        acc7 += __shfl_xor_sync(0xFFFFFFFF, acc7, o);
        den  += __shfl_xor_sync(0xFFFFFFFF, den, o);
    }

    float inv = (den > 0.f) ? (1.0f / den) : 0.f;
    const float4 ha = *(const float4*)(d_h + rowbase + sub * 8);
    const float4 hb = *(const float4*)(d_h + rowbase + sub * 8 + 4);
    const float4 sa = *(const float4*)(d_s + rowbase + sub * 8);
    const float4 sb = *(const float4*)(d_s + rowbase + sub * 8 + 4);
    float v0 = ha.x + acc0 * inv + sa.x;
    float v1 = ha.y + acc1 * inv + sa.y;
    float v2 = ha.z + acc2 * inv + sa.z;
    float v3 = ha.w + acc3 * inv + sa.w;
    float v4 = hb.x + acc4 * inv + sb.x;
    float v5 = hb.y + acc5 * inv + sb.y;
    float v6 = hb.z + acc6 * inv + sb.z;
    float v7 = hb.w + acc7 * inv + sb.w;

    float sum = ((v0 + v1) + (v2 + v3)) + ((v4 + v5) + (v6 + v7));
    float sq = ((v0 * v0 + v1 * v1) + (v2 * v2 + v3 * v3))
             + ((v4 * v4 + v5 * v5) + (v6 * v6 + v7 * v7));
#pragma unroll
    for (int o = 16; o > 0; o >>= 1) {
        sum += __shfl_xor_sync(0xFFFFFFFF, sum, o);
        sq  += __shfl_xor_sync(0xFFFFFFFF, sq, o);
    }
    // each dim counted 4 times (quarter duplication): 64 * 4 = 256
    float mean = sum * (1.0f / 256.0f);
    float var = sq * (1.0f / 256.0f) - mean * mean;
    float rs = rsqrtf(var + EPSF);

    const float4 ga = *(const float4*)(g + sub * 8);
    const float4 gb = *(const float4*)(g + sub * 8 + 4);
    const float4 ba = *(const float4*)(bta + sub * 8);
    const float4 bb2 = *(const float4*)(bta + sub * 8 + 4);
    float o0 = (v0 - mean) * rs * ga.x + ba.x;
    float o1 = (v1 - mean) * rs * ga.y + ba.y;
    float o2 = (v2 - mean) * rs * ga.z + ba.z;
    float o3 = (v3 - mean) * rs * ga.w + ba.w;
    float o4 = (v4 - mean) * rs * gb.x + bb2.x;
    float o5 = (v5 - mean) * rs * gb.y + bb2.y;
    float o6 = (v6 - mean) * rs * gb.z + bb2.z;
    float o7 = (v7 - mean) * rs * gb.w + bb2.w;

    if (quarter == 0) {
        *(float4*)(d_h + rowbase + sub * 8) = make_float4(o0, o1, o2, o3);
        *(float4*)(d_h + rowbase + sub * 8 + 4) = make_float4(o4, o5, o6, o7);
        __half2 h2[4];
        h2[0] = __floats2half2_rn(o0, o1);
        h2[1] = __floats2half2_rn(o2, o3);
        h2[2] = __floats2half2_rn(o4, o5);
        h2[3] = __floats2half2_rn(o6, o7);
        *(uint4*)(d_h16 + rowbase + sub * 8) = *(uint4*)h2;
    }
}

__global__ void out_proj_kernel(const float* __restrict__ oW,
                                const float* __restrict__ ob,
                                float* __restrict__ out) {
    int t = blockIdx.x * blockDim.x + threadIdx.x;
    if (t >= BN) return;
    int b = t / NN, n = t % NN;
    const float4* hr = (const float4*)(d_h + (size_t)t * 64);
    float a0 = ob[0], a1 = ob[1], a2 = ob[2];
#pragma unroll
    for (int i = 0; i < 16; i++) {
        float4 hv = hr[i];
        int h0 = i * 4;
        a0 += hv.x * oW[(h0 + 0) * PP + 0]; a1 += hv.x * oW[(h0 + 0) * PP + 1]; a2 += hv.x * oW[(h0 + 0) * PP + 2];
        a0 += hv.y * oW[(h0 + 1) * PP + 0]; a1 += hv.y * oW[(h0 + 1) * PP + 1]; a2 += hv.y * oW[(h0 + 1) * PP + 2];
        a0 += hv.z * oW[(h0 + 2) * PP + 0]; a1 += hv.z * oW[(h0 + 2) * PP + 1]; a2 += hv.z * oW[(h0 + 2) * PP + 2];
        a0 += hv.w * oW[(h0 + 3) * PP + 0]; a1 += hv.w * oW[(h0 + 3) * PP + 1]; a2 += hv.w * oW[(h0 + 3) * PP + 2];
    }
    out[(size_t)b * PP * NN + 0 * NN + n] = a0;
    out[(size_t)b * PP * NN + 1 * NN + n] = a1;
    out[(size_t)b * PP * NN + 2 * NN + n] = a2;
}

extern "C" void kernel_launch(void* const* d_in, const int* in_sizes, int n_in,
                              void* d_out, int out_size) {
    const float* x    = (const float*)d_in[0];
    const void*  ei   = d_in[1];
    const float* inW  = (const float*)d_in[2];
    const float* inb  = (const float*)d_in[3];
    const float* Wq   = (const float*)d_in[4];
    const float* bq   = (const float*)d_in[5];
    const float* Wk   = (const float*)d_in[6];
    const float* bk   = (const float*)d_in[7];
    const float* Wv   = (const float*)d_in[8];
    const float* bv   = (const float*)d_in[9];
    const float* Wsk  = (const float*)d_in[10];
    const float* bsk  = (const float*)d_in[11];
    const float* lng  = (const float*)d_in[12];
    const float* lnb  = (const float*)d_in[13];
    const float* oW   = (const float*)d_in[14];
    const float* ob   = (const float*)d_in[15];
    float* out = (float*)d_out;

    detect_kernel<<<1, 1>>>(ei);
    zero_deg_kernel<<<(NN + 255) / 256, 256>>>();
    convert_kernel<<<EE / 256, 256>>>(ei);
    scan_kernel<<<1, 1024>>>();
    scatter_kernel<<<EE / 256, 256>>>();
    convw_kernel<<<(LL * 4 * 4096 + 255) / 256, 256>>>(Wq, Wk, Wv, Wsk);

    dim3 ipg((NN + 63) / 64, BB);
    input_proj_kernel<<<ipg, 256>>>(x, inW, inb);

    for (int l = 0; l < LL; l++) {
        gemm_wmma_kernel<<<BN / 64, 512>>>(l, bq + l * HH, bk + l * HH,
                                           bv + l * HH, bsk + l * HH);
        edge_node_kernel<<<BN / 8, 256>>>(lng, lnb);
    }

    out_proj_kernel<<<(BN + 255) / 256, 256>>>(oW, ob, out);
}

// round 10
// speedup vs baseline: 2.5851x; 1.0400x over previous
#include <cuda_runtime.h>
#include <cuda_fp16.h>
#include <mma.h>
#include <math.h>

using namespace nvcuda;

#define NN 10000
#define EE 320000
#define BB 8
#define SS 12
#define HH 64
#define HEADS 4
#define CC 16
#define LL 3
#define PP 3
#define BN (BB * NN)
#define EPSF 1e-5f

__device__ __align__(16) float d_h[BN * HH];
__device__ __align__(16) __half d_h16[BN * HH];
__device__ __align__(16) float d_q[BN * HH];
__device__ __align__(16) float d_s[BN * HH];
__device__ __align__(16) __half d_k16[BN * HH];
__device__ __align__(16) __half d_v16[BN * HH];
__device__ __align__(16) __half d_W16all[LL * 4 * HH * HH];
__device__ int d_src[EE];
__device__ int d_dst[EE];
__device__ int d_deg[NN];
__device__ int d_ptr[NN + 1];
__device__ int d_cnt[NN];
__device__ int d_csr_src[EE];
__device__ int d_is64;

__global__ void detect_kernel(const void* ei) {
    const long long* p = (const long long*)ei;
    int is64 = 1;
    for (int i = 0; i < 64; i++) {
        long long v = p[i];
        if (v < 0 || v >= NN) { is64 = 0; break; }
    }
    d_is64 = is64;
}

__global__ void zero_deg_kernel() {
    int i = blockIdx.x * blockDim.x + threadIdx.x;
    if (i < NN) d_deg[i] = 0;
}

__global__ void convert_kernel(const void* ei) {
    int e = blockIdx.x * blockDim.x + threadIdx.x;
    if (e >= EE) return;
    int s, d;
    if (d_is64) {
        const long long* p = (const long long*)ei;
        s = (int)p[e];
        d = (int)p[EE + e];
    } else {
        const int* p = (const int*)ei;
        s = p[e];
        d = p[EE + e];
    }
    d_src[e] = s;
    d_dst[e] = d;
    atomicAdd(&d_deg[d], 1);
}

// coalesced smem staging + block scan of d_deg -> d_ptr (exclusive), d_cnt copy
__global__ void scan_kernel() {
    __shared__ int sdeg[10240];
    __shared__ int wsums[32];
    int tid = threadIdx.x;
    for (int idx = tid; idx < 10240; idx += 1024)
        sdeg[idx] = (idx < NN) ? d_deg[idx] : 0;
    __syncthreads();
    const int PER = 10;
    int start = tid * PER;
    int local = 0;
#pragma unroll
    for (int i = 0; i < PER; i++) local += sdeg[start + i];
    int lane = tid & 31, wid = tid >> 5;
    int scan = local;
#pragma unroll
    for (int o = 1; o < 32; o <<= 1) {
        int t = __shfl_up_sync(0xFFFFFFFF, scan, o);
        if (lane >= o) scan += t;
    }
    if (lane == 31) wsums[wid] = scan;
    __syncthreads();
    if (wid == 0) {
        int v = wsums[lane];
#pragma unroll
        for (int o = 1; o < 32; o <<= 1) {
            int t = __shfl_up_sync(0xFFFFFFFF, v, o);
            if (lane >= o) v += t;
        }
        wsums[lane] = v;
    }
    __syncthreads();
    int excl = scan - local + ((wid > 0) ? wsums[wid - 1] : 0);
#pragma unroll
    for (int i = 0; i < PER; i++) {
        int idx = start + i;
        if (idx < NN) {
            d_ptr[idx] = excl;
            d_cnt[idx] = excl;
            excl += sdeg[idx];
        }
    }
    if (tid == 1023) d_ptr[NN] = EE;
}

__global__ void scatter_kernel() {
    int e = blockIdx.x * blockDim.x + threadIdx.x;
    if (e >= EE) return;
    int d = d_dst[e];
    int pos = atomicAdd(&d_cnt[d], 1);
    d_csr_src[pos] = d_src[e];
}

__global__ void convw_kernel(const float* __restrict__ Wq, const float* __restrict__ Wk,
                             const float* __restrict__ Wv, const float* __restrict__ Wsk) {
    int idx = blockIdx.x * blockDim.x + threadIdx.x;
    if (idx >= LL * 4 * 4096) return;
    int l = idx >> 14;
    int sel = (idx >> 12) & 3;
    int j = idx & 4095;
    const float* W = (sel == 0) ? Wq : (sel == 1) ? Wk : (sel == 2) ? Wv : Wsk;
    d_W16all[idx] = __float2half(W[l * 4096 + j]);
}

__global__ void input_proj_kernel(const float* __restrict__ x,
                                  const float* __restrict__ inW,
                                  const float* __restrict__ inb) {
    __shared__ float xs[SS * 64];
    __shared__ float Ws[SS * HH];
    int b = blockIdx.y;
    int nb = blockIdx.x * 64;
    int tid = threadIdx.x;
    for (int idx = tid; idx < SS * HH; idx += 256) Ws[idx] = inW[idx];
    for (int idx = tid; idx < SS * 64; idx += 256) {
        int s = idx >> 6, i = idx & 63;
        int n = nb + i;
        xs[idx] = (n < NN) ? x[(size_t)b * SS * NN + s * NN + n] : 0.0f;
    }
    __syncthreads();
    int j = tid & 63;
    int i0 = (tid >> 6) * 16;
    float bj = inb[j];
    for (int ii = 0; ii < 16; ii++) {
        int i = i0 + ii;
        int n = nb + i;
        if (n >= NN) break;
        float acc = bj;
#pragma unroll
        for (int s = 0; s < SS; s++) acc += xs[s * 64 + i] * Ws[s * HH + j];
        size_t o = ((size_t)b * NN + n) * HH + j;
        d_h[o] = acc;
        d_h16[o] = __float2half(acc);
    }
}

// 512 threads = 16 warps: warp = rowtile(0-3) + 4*sel(0-3). 64 rows per block.
// A tile staged once through smem (ld=72 to spread banks).
__global__ void gemm_wmma_kernel(int layer,
                                 const float* __restrict__ b0, const float* __restrict__ b1,
                                 const float* __restrict__ b2, const float* __restrict__ b3) {
    __shared__ __half As[64 * 72];
    __shared__ float stage[16][256];
    int tid = threadIdx.x;
    int warp = tid >> 5;
    int lane = tid & 31;
    int rt = warp & 3;
    int wsel = warp >> 2;
    int base0 = blockIdx.x * 64;
    int base = base0 + rt * 16;

    {
        int row = tid >> 3, col = (tid & 7) * 8;
        uint4 vsrc = *(const uint4*)(d_h16 + (size_t)(base0 + row) * 64 + col);
        *(uint4*)(As + row * 72 + col) = vsrc;
    }
    __syncthreads();

    const __half* B = d_W16all + ((size_t)layer * 4 + wsel) * 4096;

    wmma::fragment<wmma::accumulator, 16, 16, 16, float> acc[4];
#pragma unroll
    for (int nt = 0; nt < 4; nt++) wmma::fill_fragment(acc[nt], 0.0f);

#pragma unroll
    for (int kk = 0; kk < 4; kk++) {
        wmma::fragment<wmma::matrix_a, 16, 16, 16, __half, wmma::row_major> a;
        wmma::load_matrix_sync(a, As + (rt * 16) * 72 + kk * 16, 72);
#pragma unroll
        for (int nt = 0; nt < 4; nt++) {
            wmma::fragment<wmma::matrix_b, 16, 16, 16, __half, wmma::row_major> b;
            wmma::load_matrix_sync(b, B + (size_t)kk * 16 * 64 + nt * 16, 64);
            wmma::mma_sync(acc[nt], a, b, acc[nt]);
        }
    }

    const float* bias = (wsel == 0) ? b0 : (wsel == 1) ? b1 : (wsel == 2) ? b2 : b3;
    float* stg = &stage[warp][0];
    int r = lane >> 1, c0 = (lane & 1) * 8;
#pragma unroll
    for (int nt = 0; nt < 4; nt++) {
        wmma::store_matrix_sync(stg, acc[nt], 16, wmma::mem_row_major);
        __syncwarp();
        int gr = base + r;
        int gc = nt * 16 + c0;
        float vals[8];
#pragma unroll
        for (int t = 0; t < 8; t++) vals[t] = stg[r * 16 + c0 + t] + bias[gc + t];
        if (wsel == 0 || wsel == 3) {
            float* outp = (wsel == 0) ? d_q : d_s;
            *(float4*)(outp + (size_t)gr * 64 + gc) = make_float4(vals[0], vals[1], vals[2], vals[3]);
            *(float4*)(outp + (size_t)gr * 64 + gc + 4) = make_float4(vals[4], vals[5], vals[6], vals[7]);
        } else {
            __half* outp = (wsel == 1) ? d_k16 : d_v16;
            __half2 h2[4];
#pragma unroll
            for (int t = 0; t < 4; t++) h2[t] = __floats2half2_rn(vals[2 * t], vals[2 * t + 1]);
            *(uint4*)(outp + (size_t)gr * 64 + gc) = *(uint4*)h2;
        }
        __syncwarp();
    }
}

// warp per (batch, node); lane = (quarter 0-3, sub 0-7); lane owns 8 dims
// (half a head) so the head dot needs one shfl. 8 edges per iteration: each
// quarter-lane owns 2 edges, all 4 LDG.128 issued before any consumption.
__global__ void __launch_bounds__(256) edge_node_kernel(const float* __restrict__ g,
                                                        const float* __restrict__ bta) {
    int w = blockIdx.x * 8 + (threadIdx.x >> 5);
    int lane = threadIdx.x & 31;
    int quarter = lane >> 3;
    int sub = lane & 7;
    int n = w % NN;
    int b = w / NN;
    int rowbase = (b * NN + n) * HH;
    int bbase = b * NN;

    const float4 qa = *(const float4*)(d_q + rowbase + sub * 8);
    const float4 qb = *(const float4*)(d_q + rowbase + sub * 8 + 4);

    int start = d_ptr[n];
    int end = d_ptr[n + 1];

    const uint4* kp = (const uint4*)d_k16;
    const uint4* vp = (const uint4*)d_v16;

    float acc0 = 0.f, acc1 = 0.f, acc2 = 0.f, acc3 = 0.f;
    float acc4 = 0.f, acc5 = 0.f, acc6 = 0.f, acc7 = 0.f;
    float den = 0.f;

    for (int i = start; i < end; i += 8) {
        int e0 = i + quarter;
        int e1 = i + 4 + quarter;
        bool va0 = (e0 < end);
        bool va1 = (e1 < end);
        int s0 = d_csr_src[va0 ? e0 : (end - 1)];
        int s1 = d_csr_src[va1 ? e1 : (end - 1)];
        size_t r0 = (size_t)(bbase + s0) * 8 + sub;
        size_t r1 = (size_t)(bbase + s1) * 8 + sub;
        uint4 ku0 = kp[r0];
        uint4 vu0 = vp[r0];
        uint4 ku1 = kp[r1];
        uint4 vu1 = vp[r1];

        float2 k00 = __half22float2(*(__half2*)&ku0.x);
        float2 k01 = __half22float2(*(__half2*)&ku0.y);
        float2 k02 = __half22float2(*(__half2*)&ku0.z);
        float2 k03 = __half22float2(*(__half2*)&ku0.w);
        float p0 = qa.x * k00.x + qa.y * k00.y + qa.z * k01.x + qa.w * k01.y
                 + qb.x * k02.x + qb.y * k02.y + qb.z * k03.x + qb.w * k03.y;
        float2 k10 = __half22float2(*(__half2*)&ku1.x);
        float2 k11 = __half22float2(*(__half2*)&ku1.y);
        float2 k12 = __half22float2(*(__half2*)&ku1.z);
        float2 k13 = __half22float2(*(__half2*)&ku1.w);
        float p1 = qa.x * k10.x + qa.y * k10.y + qa.z * k11.x + qa.w * k11.y
                 + qb.x * k12.x + qb.y * k12.y + qb.z * k13.x + qb.w * k13.y;
        p0 += __shfl_xor_sync(0xFFFFFFFF, p0, 1);
        p1 += __shfl_xor_sync(0xFFFFFFFF, p1, 1);
        float wt0 = va0 ? __expf(p0 * 0.25f) : 0.f;
        float wt1 = va1 ? __expf(p1 * 0.25f) : 0.f;
        den += wt0 + wt1;

        float2 v00 = __half22float2(*(__half2*)&vu0.x);
        float2 v01 = __half22float2(*(__half2*)&vu0.y);
        float2 v02 = __half22float2(*(__half2*)&vu0.z);
        float2 v03 = __half22float2(*(__half2*)&vu0.w);
        float2 v10 = __half22float2(*(__half2*)&vu1.x);
        float2 v11 = __half22float2(*(__half2*)&vu1.y);
        float2 v12 = __half22float2(*(__half2*)&vu1.z);
        float2 v13 = __half22float2(*(__half2*)&vu1.w);
        acc0 += wt0 * v00.x + wt1 * v10.x;
        acc1 += wt0 * v00.y + wt1 * v10.y;
        acc2 += wt0 * v01.x + wt1 * v11.x;
        acc3 += wt0 * v01.y + wt1 * v11.y;
        acc4 += wt0 * v02.x + wt1 * v12.x;
        acc5 += wt0 * v02.y + wt1 * v12.y;
        acc6 += wt0 * v03.x + wt1 * v13.x;
        acc7 += wt0 * v03.y + wt1 * v13.y;
    }

#pragma unroll
    for (int o = 8; o <= 16; o <<= 1) {
        acc0 += __shfl_xor_sync(0xFFFFFFFF, acc0, o);
        acc1 += __shfl_xor_sync(0xFFFFFFFF, acc1, o);
        acc2 += __shfl_xor_sync(0xFFFFFFFF, acc2, o);
        acc3 += __shfl_xor_sync(0xFFFFFFFF, acc3, o);
        acc4 += __shfl_xor_sync(0xFFFFFFFF, acc4, o);
        acc5 += __shfl_xor_sync(0xFFFFFFFF, acc5, o);
        acc6 += __shfl_xor_sync(0xFFFFFFFF, acc6, o);
        acc7 += __shfl_xor_sync(0xFFFFFFFF, acc7, o);
        den  += __shfl_xor_sync(0xFFFFFFFF, den, o);
    }

    float inv = (den > 0.f) ? (1.0f / den) : 0.f;
    const float4 ha = *(const float4*)(d_h + rowbase + sub * 8);
    const float4 hb = *(const float4*)(d_h + rowbase + sub * 8 + 4);
    const float4 sa = *(const float4*)(d_s + rowbase + sub * 8);
    const float4 sb = *(const float4*)(d_s + rowbase + sub * 8 + 4);
    float v0 = ha.x + acc0 * inv + sa.x;
    float v1 = ha.y + acc1 * inv + sa.y;
    float v2 = ha.z + acc2 * inv + sa.z;
    float v3 = ha.w + acc3 * inv + sa.w;
    float v4 = hb.x + acc4 * inv + sb.x;
    float v5 = hb.y + acc5 * inv + sb.y;
    float v6 = hb.z + acc6 * inv + sb.z;
    float v7 = hb.w + acc7 * inv + sb.w;

    float sum = ((v0 + v1) + (v2 + v3)) + ((v4 + v5) + (v6 + v7));
    float sq = ((v0 * v0 + v1 * v1) + (v2 * v2 + v3 * v3))
             + ((v4 * v4 + v5 * v5) + (v6 * v6 + v7 * v7));
#pragma unroll
    for (int o = 16; o > 0; o >>= 1) {
        sum += __shfl_xor_sync(0xFFFFFFFF, sum, o);
        sq  += __shfl_xor_sync(0xFFFFFFFF, sq, o);
    }
    float mean = sum * (1.0f / 256.0f);
    float var = sq * (1.0f / 256.0f) - mean * mean;
    float rs = rsqrtf(var + EPSF);

    const float4 ga = *(const float4*)(g + sub * 8);
    const float4 gb = *(const float4*)(g + sub * 8 + 4);
    const float4 ba = *(const float4*)(bta + sub * 8);
    const float4 bb2 = *(const float4*)(bta + sub * 8 + 4);
    float o0 = (v0 - mean) * rs * ga.x + ba.x;
    float o1 = (v1 - mean) * rs * ga.y + ba.y;
    float o2 = (v2 - mean) * rs * ga.z + ba.z;
    float o3 = (v3 - mean) * rs * ga.w + ba.w;
    float o4 = (v4 - mean) * rs * gb.x + bb2.x;
    float o5 = (v5 - mean) * rs * gb.y + bb2.y;
    float o6 = (v6 - mean) * rs * gb.z + bb2.z;
    float o7 = (v7 - mean) * rs * gb.w + bb2.w;

    if (quarter == 0) {
        *(float4*)(d_h + rowbase + sub * 8) = make_float4(o0, o1, o2, o3);
        *(float4*)(d_h + rowbase + sub * 8 + 4) = make_float4(o4, o5, o6, o7);
        __half2 h2[4];
        h2[0] = __floats2half2_rn(o0, o1);
        h2[1] = __floats2half2_rn(o2, o3);
        h2[2] = __floats2half2_rn(o4, o5);
        h2[3] = __floats2half2_rn(o6, o7);
        *(uint4*)(d_h16 + rowbase + sub * 8) = *(uint4*)h2;
    }
}

__global__ void out_proj_kernel(const float* __restrict__ oW,
                                const float* __restrict__ ob,
                                float* __restrict__ out) {
    int t = blockIdx.x * blockDim.x + threadIdx.x;
    if (t >= BN) return;
    int b = t / NN, n = t % NN;
    const float4* hr = (const float4*)(d_h + (size_t)t * 64);
    float a0 = ob[0], a1 = ob[1], a2 = ob[2];
#pragma unroll
    for (int i = 0; i < 16; i++) {
        float4 hv = hr[i];
        int h0 = i * 4;
        a0 += hv.x * oW[(h0 + 0) * PP + 0]; a1 += hv.x * oW[(h0 + 0) * PP + 1]; a2 += hv.x * oW[(h0 + 0) * PP + 2];
        a0 += hv.y * oW[(h0 + 1) * PP + 0]; a1 += hv.y * oW[(h0 + 1) * PP + 1]; a2 += hv.y * oW[(h0 + 1) * PP + 2];
        a0 += hv.z * oW[(h0 + 2) * PP + 0]; a1 += hv.z * oW[(h0 + 2) * PP + 1]; a2 += hv.z * oW[(h0 + 2) * PP + 2];
        a0 += hv.w * oW[(h0 + 3) * PP + 0]; a1 += hv.w * oW[(h0 + 3) * PP + 1]; a2 += hv.w * oW[(h0 + 3) * PP + 2];
    }
    out[(size_t)b * PP * NN + 0 * NN + n] = a0;
    out[(size_t)b * PP * NN + 1 * NN + n] = a1;
    out[(size_t)b * PP * NN + 2 * NN + n] = a2;
}

extern "C" void kernel_launch(void* const* d_in, const int* in_sizes, int n_in,
                              void* d_out, int out_size) {
    const float* x    = (const float*)d_in[0];
    const void*  ei   = d_in[1];
    const float* inW  = (const float*)d_in[2];
    const float* inb  = (const float*)d_in[3];
    const float* Wq   = (const float*)d_in[4];
    const float* bq   = (const float*)d_in[5];
    const float* Wk   = (const float*)d_in[6];
    const float* bk   = (const float*)d_in[7];
    const float* Wv   = (const float*)d_in[8];
    const float* bv   = (const float*)d_in[9];
    const float* Wsk  = (const float*)d_in[10];
    const float* bsk  = (const float*)d_in[11];
    const float* lng  = (const float*)d_in[12];
    const float* lnb  = (const float*)d_in[13];
    const float* oW   = (const float*)d_in[14];
    const float* ob   = (const float*)d_in[15];
    float* out = (float*)d_out;

    detect_kernel<<<1, 1>>>(ei);
    zero_deg_kernel<<<(NN + 255) / 256, 256>>>();
    convert_kernel<<<EE / 256, 256>>>(ei);
    scan_kernel<<<1, 1024>>>();
    scatter_kernel<<<EE / 256, 256>>>();
    convw_kernel<<<(LL * 4 * 4096 + 255) / 256, 256>>>(Wq, Wk, Wv, Wsk);

    dim3 ipg((NN + 63) / 64, BB);
    input_proj_kernel<<<ipg, 256>>>(x, inW, inb);

    for (int l = 0; l < LL; l++) {
        gemm_wmma_kernel<<<BN / 64, 512>>>(l, bq + l * HH, bk + l * HH,
                                           bv + l * HH, bsk + l * HH);
        edge_node_kernel<<<BN / 8, 256>>>(lng, lnb);
    }

    out_proj_kernel<<<(BN + 255) / 256, 256>>>(oW, ob, out);
}

// round 12
// speedup vs baseline: 2.8612x; 1.1068x over previous
#include <cuda_runtime.h>
#include <cuda_fp16.h>
#include <mma.h>
#include <math.h>

using namespace nvcuda;

#define NN 10000
#define EE 320000
#define BB 8
#define SS 12
#define HH 64
#define HEADS 4
#define CC 16
#define LL 3
#define PP 3
#define BN (BB * NN)
#define EPSF 1e-5f

__device__ __align__(16) float d_h[BN * HH];
__device__ __align__(16) __half d_h16[BN * HH];
__device__ __align__(16) float d_q[BN * HH];
__device__ __align__(16) float d_s[BN * HH];
// node-major: [n][b][64]
__device__ __align__(16) __half d_k16[BN * HH];
__device__ __align__(16) __half d_v16[BN * HH];
__device__ __align__(16) __half d_W16all[LL * 4 * HH * HH];
__device__ int d_src[EE];
__device__ int d_dst[EE];
__device__ int d_deg[NN];
__device__ int d_ptr[NN + 1];
__device__ int d_cnt[NN];
__device__ int d_csr_src[EE];
__device__ int d_is64;

__global__ void detect_kernel(const void* ei) {
    const long long* p = (const long long*)ei;
    int is64 = 1;
    for (int i = 0; i < 64; i++) {
        long long v = p[i];
        if (v < 0 || v >= NN) { is64 = 0; break; }
    }
    d_is64 = is64;
}

__global__ void zero_deg_kernel() {
    int i = blockIdx.x * blockDim.x + threadIdx.x;
    if (i < NN) d_deg[i] = 0;
}

__global__ void convert_kernel(const void* ei) {
    int e = blockIdx.x * blockDim.x + threadIdx.x;
    if (e >= EE) return;
    int s, d;
    if (d_is64) {
        const long long* p = (const long long*)ei;
        s = (int)p[e];
        d = (int)p[EE + e];
    } else {
        const int* p = (const int*)ei;
        s = p[e];
        d = p[EE + e];
    }
    d_src[e] = s;
    d_dst[e] = d;
    atomicAdd(&d_deg[d], 1);
}

__global__ void scan_kernel() {
    __shared__ int sdeg[10240];
    __shared__ int wsums[32];
    int tid = threadIdx.x;
    for (int idx = tid; idx < 10240; idx += 1024)
        sdeg[idx] = (idx < NN) ? d_deg[idx] : 0;
    __syncthreads();
    const int PER = 10;
    int start = tid * PER;
    int local = 0;
#pragma unroll
    for (int i = 0; i < PER; i++) local += sdeg[start + i];
    int lane = tid & 31, wid = tid >> 5;
    int scan = local;
#pragma unroll
    for (int o = 1; o < 32; o <<= 1) {
        int t = __shfl_up_sync(0xFFFFFFFF, scan, o);
        if (lane >= o) scan += t;
    }
    if (lane == 31) wsums[wid] = scan;
    __syncthreads();
    if (wid == 0) {
        int v = wsums[lane];
#pragma unroll
        for (int o = 1; o < 32; o <<= 1) {
            int t = __shfl_up_sync(0xFFFFFFFF, v, o);
            if (lane >= o) v += t;
        }
        wsums[lane] = v;
    }
    __syncthreads();
    int excl = scan - local + ((wid > 0) ? wsums[wid - 1] : 0);
#pragma unroll
    for (int i = 0; i < PER; i++) {
        int idx = start + i;
        if (idx < NN) {
            d_ptr[idx] = excl;
            d_cnt[idx] = excl;
            excl += sdeg[idx];
        }
    }
    if (tid == 1023) d_ptr[NN] = EE;
}

__global__ void scatter_kernel() {
    int e = blockIdx.x * blockDim.x + threadIdx.x;
    if (e >= EE) return;
    int d = d_dst[e];
    int pos = atomicAdd(&d_cnt[d], 1);
    d_csr_src[pos] = d_src[e];
}

__global__ void convw_kernel(const float* __restrict__ Wq, const float* __restrict__ Wk,
                             const float* __restrict__ Wv, const float* __restrict__ Wsk) {
    int idx = blockIdx.x * blockDim.x + threadIdx.x;
    if (idx >= LL * 4 * 4096) return;
    int l = idx >> 14;
    int sel = (idx >> 12) & 3;
    int j = idx & 4095;
    const float* W = (sel == 0) ? Wq : (sel == 1) ? Wk : (sel == 2) ? Wv : Wsk;
    d_W16all[idx] = __float2half(W[l * 4096 + j]);
}

__global__ void input_proj_kernel(const float* __restrict__ x,
                                  const float* __restrict__ inW,
                                  const float* __restrict__ inb) {
    __shared__ float xs[SS * 64];
    __shared__ float Ws[SS * HH];
    int b = blockIdx.y;
    int nb = blockIdx.x * 64;
    int tid = threadIdx.x;
    for (int idx = tid; idx < SS * HH; idx += 256) Ws[idx] = inW[idx];
    for (int idx = tid; idx < SS * 64; idx += 256) {
        int s = idx >> 6, i = idx & 63;
        int n = nb + i;
        xs[idx] = (n < NN) ? x[(size_t)b * SS * NN + s * NN + n] : 0.0f;
    }
    __syncthreads();
    int j = tid & 63;
    int i0 = (tid >> 6) * 16;
    float bj = inb[j];
    for (int ii = 0; ii < 16; ii++) {
        int i = i0 + ii;
        int n = nb + i;
        if (n >= NN) break;
        float acc = bj;
#pragma unroll
        for (int s = 0; s < SS; s++) acc += xs[s * 64 + i] * Ws[s * HH + j];
        size_t o = ((size_t)b * NN + n) * HH + j;
        d_h[o] = acc;
        d_h16[o] = __float2half(acc);
    }
}

// 512 threads = 16 warps: warp = rowtile(0-3) + 4*sel(0-3). 64 rows per block.
// k/v written node-major [n][b][64]; q/s batch-major fp32.
__global__ void gemm_wmma_kernel(int layer,
                                 const float* __restrict__ b0, const float* __restrict__ b1,
                                 const float* __restrict__ b2, const float* __restrict__ b3) {
    __shared__ __half As[64 * 72];
    __shared__ float stage[16][256];
    int tid = threadIdx.x;
    int warp = tid >> 5;
    int lane = tid & 31;
    int rt = warp & 3;
    int wsel = warp >> 2;
    int base0 = blockIdx.x * 64;
    int base = base0 + rt * 16;

    {
        int row = tid >> 3, col = (tid & 7) * 8;
        uint4 vsrc = *(const uint4*)(d_h16 + (size_t)(base0 + row) * 64 + col);
        *(uint4*)(As + row * 72 + col) = vsrc;
    }
    __syncthreads();

    const __half* B = d_W16all + ((size_t)layer * 4 + wsel) * 4096;

    wmma::fragment<wmma::accumulator, 16, 16, 16, float> acc[4];
#pragma unroll
    for (int nt = 0; nt < 4; nt++) wmma::fill_fragment(acc[nt], 0.0f);

#pragma unroll
    for (int kk = 0; kk < 4; kk++) {
        wmma::fragment<wmma::matrix_a, 16, 16, 16, __half, wmma::row_major> a;
        wmma::load_matrix_sync(a, As + (rt * 16) * 72 + kk * 16, 72);
#pragma unroll
        for (int nt = 0; nt < 4; nt++) {
            wmma::fragment<wmma::matrix_b, 16, 16, 16, __half, wmma::row_major> b;
            wmma::load_matrix_sync(b, B + (size_t)kk * 16 * 64 + nt * 16, 64);
            wmma::mma_sync(acc[nt], a, b, acc[nt]);
        }
    }

    const float* bias = (wsel == 0) ? b0 : (wsel == 1) ? b1 : (wsel == 2) ? b2 : b3;
    float* stg = &stage[warp][0];
    int r = lane >> 1, c0 = (lane & 1) * 8;
    int gr = base + r;
    int gb = gr / NN;
    int gn = gr - gb * NN;
    size_t kvrow = ((size_t)gn * BB + gb) * 64;   // node-major row for k/v
#pragma unroll
    for (int nt = 0; nt < 4; nt++) {
        wmma::store_matrix_sync(stg, acc[nt], 16, wmma::mem_row_major);
        __syncwarp();
        int gc = nt * 16 + c0;
        float vals[8];
#pragma unroll
        for (int t = 0; t < 8; t++) vals[t] = stg[r * 16 + c0 + t] + bias[gc + t];
        if (wsel == 0 || wsel == 3) {
            float* outp = (wsel == 0) ? d_q : d_s;
            *(float4*)(outp + (size_t)gr * 64 + gc) = make_float4(vals[0], vals[1], vals[2], vals[3]);
            *(float4*)(outp + (size_t)gr * 64 + gc + 4) = make_float4(vals[4], vals[5], vals[6], vals[7]);
        } else {
            __half* outp = (wsel == 1) ? d_k16 : d_v16;
            __half2 h2[4];
#pragma unroll
            for (int t = 0; t < 4; t++) h2[t] = __floats2half2_rn(vals[2 * t], vals[2 * t + 1]);
            *(uint4*)(outp + kvrow + gc) = *(uint4*)h2;
        }
        __syncwarp();
    }
}

// warp per NODE. lane = b*4 + head (b 0-7, head 0-3). Lane owns head's 16
// dims for batch b: dot + weight + v-accumulation fully in-lane (no shfls
// in loop). k/v node-major: one edge = contiguous 1KB per tensor. CSR read
// once per node (broadcast). LN: 2 shfls across head lanes.
__global__ void __launch_bounds__(256) edge_node_kernel(const float* __restrict__ g,
                                                        const float* __restrict__ bta) {
    int n = blockIdx.x * 8 + (threadIdx.x >> 5);
    int lane = threadIdx.x & 31;
    int b = lane >> 2;
    int head = lane & 3;
    int rowbase = (b * NN + n) * HH + head * CC;   // batch-major (q,h,s)
    int kvoff = b * HH + head * CC;                // within node block (halves)

    const float4 q0 = *(const float4*)(d_q + rowbase);
    const float4 q1 = *(const float4*)(d_q + rowbase + 4);
    const float4 q2 = *(const float4*)(d_q + rowbase + 8);
    const float4 q3 = *(const float4*)(d_q + rowbase + 12);

    int start = d_ptr[n];
    int end = d_ptr[n + 1];

    float ac0 = 0.f, ac1 = 0.f, ac2 = 0.f, ac3 = 0.f;
    float ac4 = 0.f, ac5 = 0.f, ac6 = 0.f, ac7 = 0.f;
    float ac8 = 0.f, ac9 = 0.f, acA = 0.f, acB = 0.f;
    float acC = 0.f, acD = 0.f, acE = 0.f, acF = 0.f;
    float den = 0.f;

    for (int i = start; i < end; i += 2) {
        int s0 = d_csr_src[i];
        bool va1 = (i + 1 < end);
        int s1 = d_csr_src[va1 ? (i + 1) : i];
        size_t a0 = (size_t)s0 * 512 + kvoff;
        size_t a1 = (size_t)s1 * 512 + kvoff;
        uint4 k0a = *(const uint4*)(d_k16 + a0);
        uint4 k0b = *(const uint4*)(d_k16 + a0 + 8);
        uint4 v0a = *(const uint4*)(d_v16 + a0);
        uint4 v0b = *(const uint4*)(d_v16 + a0 + 8);
        uint4 k1a = *(const uint4*)(d_k16 + a1);
        uint4 k1b = *(const uint4*)(d_k16 + a1 + 8);
        uint4 v1a = *(const uint4*)(d_v16 + a1);
        uint4 v1b = *(const uint4*)(d_v16 + a1 + 8);

        {
            float2 c0 = __half22float2(*(__half2*)&k0a.x);
            float2 c1 = __half22float2(*(__half2*)&k0a.y);
            float2 c2 = __half22float2(*(__half2*)&k0a.z);
            float2 c3 = __half22float2(*(__half2*)&k0a.w);
            float2 c4 = __half22float2(*(__half2*)&k0b.x);
            float2 c5 = __half22float2(*(__half2*)&k0b.y);
            float2 c6 = __half22float2(*(__half2*)&k0b.z);
            float2 c7 = __half22float2(*(__half2*)&k0b.w);
            float p = q0.x * c0.x + q0.y * c0.y + q0.z * c1.x + q0.w * c1.y
                    + q1.x * c2.x + q1.y * c2.y + q1.z * c3.x + q1.w * c3.y
                    + q2.x * c4.x + q2.y * c4.y + q2.z * c5.x + q2.w * c5.y
                    + q3.x * c6.x + q3.y * c6.y + q3.z * c7.x + q3.w * c7.y;
            float wt = __expf(p * 0.25f);
            den += wt;
            float2 w0 = __half22float2(*(__half2*)&v0a.x);
            float2 w1 = __half22float2(*(__half2*)&v0a.y);
            float2 w2 = __half22float2(*(__half2*)&v0a.z);
            float2 w3 = __half22float2(*(__half2*)&v0a.w);
            float2 w4 = __half22float2(*(__half2*)&v0b.x);
            float2 w5 = __half22float2(*(__half2*)&v0b.y);
            float2 w6 = __half22float2(*(__half2*)&v0b.z);
            float2 w7 = __half22float2(*(__half2*)&v0b.w);
            ac0 += wt * w0.x; ac1 += wt * w0.y; ac2 += wt * w1.x; ac3 += wt * w1.y;
            ac4 += wt * w2.x; ac5 += wt * w2.y; ac6 += wt * w3.x; ac7 += wt * w3.y;
            ac8 += wt * w4.x; ac9 += wt * w4.y; acA += wt * w5.x; acB += wt * w5.y;
            acC += wt * w6.x; acD += wt * w6.y; acE += wt * w7.x; acF += wt * w7.y;
        }
        {
            float2 c0 = __half22float2(*(__half2*)&k1a.x);
            float2 c1 = __half22float2(*(__half2*)&k1a.y);
            float2 c2 = __half22float2(*(__half2*)&k1a.z);
            float2 c3 = __half22float2(*(__half2*)&k1a.w);
            float2 c4 = __half22float2(*(__half2*)&k1b.x);
            float2 c5 = __half22float2(*(__half2*)&k1b.y);
            float2 c6 = __half22float2(*(__half2*)&k1b.z);
            float2 c7 = __half22float2(*(__half2*)&k1b.w);
            float p = q0.x * c0.x + q0.y * c0.y + q0.z * c1.x + q0.w * c1.y
                    + q1.x * c2.x + q1.y * c2.y + q1.z * c3.x + q1.w * c3.y
                    + q2.x * c4.x + q2.y * c4.y + q2.z * c5.x + q2.w * c5.y
                    + q3.x * c6.x + q3.y * c6.y + q3.z * c7.x + q3.w * c7.y;
            float wt = va1 ? __expf(p * 0.25f) : 0.f;
            den += wt;
            float2 w0 = __half22float2(*(__half2*)&v1a.x);
            float2 w1 = __half22float2(*(__half2*)&v1a.y);
            float2 w2 = __half22float2(*(__half2*)&v1a.z);
            float2 w3 = __half22float2(*(__half2*)&v1a.w);
            float2 w4 = __half22float2(*(__half2*)&v1b.x);
            float2 w5 = __half22float2(*(__half2*)&v1b.y);
            float2 w6 = __half22float2(*(__half2*)&v1b.z);
            float2 w7 = __half22float2(*(__half2*)&v1b.w);
            ac0 += wt * w0.x; ac1 += wt * w0.y; ac2 += wt * w1.x; ac3 += wt * w1.y;
            ac4 += wt * w2.x; ac5 += wt * w2.y; ac6 += wt * w3.x; ac7 += wt * w3.y;
            ac8 += wt * w4.x; ac9 += wt * w4.y; acA += wt * w5.x; acB += wt * w5.y;
            acC += wt * w6.x; acD += wt * w6.y; acE += wt * w7.x; acF += wt * w7.y;
        }
    }

    float inv = (den > 0.f) ? (1.0f / den) : 0.f;
    const float4 h0 = *(const float4*)(d_h + rowbase);
    const float4 h1 = *(const float4*)(d_h + rowbase + 4);
    const float4 h2 = *(const float4*)(d_h + rowbase + 8);
    const float4 h3 = *(const float4*)(d_h + rowbase + 12);
    const float4 s0 = *(const float4*)(d_s + rowbase);
    const float4 s1 = *(const float4*)(d_s + rowbase + 4);
    const float4 s2 = *(const float4*)(d_s + rowbase + 8);
    const float4 s3 = *(const float4*)(d_s + rowbase + 12);

    float t0 = h0.x + ac0 * inv + s0.x;
    float t1 = h0.y + ac1 * inv + s0.y;
    float t2 = h0.z + ac2 * inv + s0.z;
    float t3 = h0.w + ac3 * inv + s0.w;
    float t4 = h1.x + ac4 * inv + s1.x;
    float t5 = h1.y + ac5 * inv + s1.y;
    float t6 = h1.z + ac6 * inv + s1.z;
    float t7 = h1.w + ac7 * inv + s1.w;
    float t8 = h2.x + ac8 * inv + s2.x;
    float t9 = h2.y + ac9 * inv + s2.y;
    float tA = h2.z + acA * inv + s2.z;
    float tB = h2.w + acB * inv + s2.w;
    float tC = h3.x + acC * inv + s3.x;
    float tD = h3.y + acD * inv + s3.y;
    float tE = h3.z + acE * inv + s3.z;
    float tF = h3.w + acF * inv + s3.w;

    float sum = ((t0 + t1) + (t2 + t3)) + ((t4 + t5) + (t6 + t7))
              + ((t8 + t9) + (tA + tB)) + ((tC + tD) + (tE + tF));
    float sq = ((t0 * t0 + t1 * t1) + (t2 * t2 + t3 * t3))
             + ((t4 * t4 + t5 * t5) + (t6 * t6 + t7 * t7))
             + ((t8 * t8 + t9 * t9) + (tA * tA + tB * tB))
             + ((tC * tC + tD * tD) + (tE * tE + tF * tF));
    sum += __shfl_xor_sync(0xFFFFFFFF, sum, 1);
    sq  += __shfl_xor_sync(0xFFFFFFFF, sq, 1);
    sum += __shfl_xor_sync(0xFFFFFFFF, sum, 2);
    sq  += __shfl_xor_sync(0xFFFFFFFF, sq, 2);

    float mean = sum * (1.0f / 64.0f);
    float var = sq * (1.0f / 64.0f) - mean * mean;
    float rs = rsqrtf(var + EPSF);

    const float4 g0 = *(const float4*)(g + head * CC);
    const float4 g1 = *(const float4*)(g + head * CC + 4);
    const float4 g2 = *(const float4*)(g + head * CC + 8);
    const float4 g3 = *(const float4*)(g + head * CC + 12);
    const float4 e0 = *(const float4*)(bta + head * CC);
    const float4 e1 = *(const float4*)(bta + head * CC + 4);
    const float4 e2 = *(const float4*)(bta + head * CC + 8);
    const float4 e3 = *(const float4*)(bta + head * CC + 12);

    float o0 = (t0 - mean) * rs * g0.x + e0.x;
    float o1 = (t1 - mean) * rs * g0.y + e0.y;
    float o2 = (t2 - mean) * rs * g0.z + e0.z;
    float o3 = (t3 - mean) * rs * g0.w + e0.w;
    float o4 = (t4 - mean) * rs * g1.x + e1.x;
    float o5 = (t5 - mean) * rs * g1.y + e1.y;
    float o6 = (t6 - mean) * rs * g1.z + e1.z;
    float o7 = (t7 - mean) * rs * g1.w + e1.w;
    float o8 = (t8 - mean) * rs * g2.x + e2.x;
    float o9 = (t9 - mean) * rs * g2.y + e2.y;
    float oA = (tA - mean) * rs * g2.z + e2.z;
    float oB = (tB - mean) * rs * g2.w + e2.w;
    float oC = (tC - mean) * rs * g3.x + e3.x;
    float oD = (tD - mean) * rs * g3.y + e3.y;
    float oE = (tE - mean) * rs * g3.z + e3.z;
    float oF = (tF - mean) * rs * g3.w + e3.w;

    *(float4*)(d_h + rowbase)      = make_float4(o0, o1, o2, o3);
    *(float4*)(d_h + rowbase + 4)  = make_float4(o4, o5, o6, o7);
    *(float4*)(d_h + rowbase + 8)  = make_float4(o8, o9, oA, oB);
    *(float4*)(d_h + rowbase + 12) = make_float4(oC, oD, oE, oF);
    __half2 hh[8];
    hh[0] = __floats2half2_rn(o0, o1);
    hh[1] = __floats2half2_rn(o2, o3);
    hh[2] = __floats2half2_rn(o4, o5);
    hh[3] = __floats2half2_rn(o6, o7);
    hh[4] = __floats2half2_rn(o8, o9);
    hh[5] = __floats2half2_rn(oA, oB);
    hh[6] = __floats2half2_rn(oC, oD);
    hh[7] = __floats2half2_rn(oE, oF);
    *(uint4*)(d_h16 + rowbase)     = *(uint4*)&hh[0];
    *(uint4*)(d_h16 + rowbase + 8) = *(uint4*)&hh[4];
}

__global__ void out_proj_kernel(const float* __restrict__ oW,
                                const float* __restrict__ ob,
                                float* __restrict__ out) {
    int t = blockIdx.x * blockDim.x + threadIdx.x;
    if (t >= BN) return;
    int b = t / NN, n = t % NN;
    const float4* hr = (const float4*)(d_h + (size_t)t * 64);
    float a0 = ob[0], a1 = ob[1], a2 = ob[2];
#pragma unroll
    for (int i = 0; i < 16; i++) {
        float4 hv = hr[i];
        int h0 = i * 4;
        a0 += hv.x * oW[(h0 + 0) * PP + 0]; a1 += hv.x * oW[(h0 + 0) * PP + 1]; a2 += hv.x * oW[(h0 + 0) * PP + 2];
        a0 += hv.y * oW[(h0 + 1) * PP + 0]; a1 += hv.y * oW[(h0 + 1) * PP + 1]; a2 += hv.y * oW[(h0 + 1) * PP + 2];
        a0 += hv.z * oW[(h0 + 2) * PP + 0]; a1 += hv.z * oW[(h0 + 2) * PP + 1]; a2 += hv.z * oW[(h0 + 2) * PP + 2];
        a0 += hv.w * oW[(h0 + 3) * PP + 0]; a1 += hv.w * oW[(h0 + 3) * PP + 1]; a2 += hv.w * oW[(h0 + 3) * PP + 2];
    }
    out[(size_t)b * PP * NN + 0 * NN + n] = a0;
    out[(size_t)b * PP * NN + 1 * NN + n] = a1;
    out[(size_t)b * PP * NN + 2 * NN + n] = a2;
}

extern "C" void kernel_launch(void* const* d_in, const int* in_sizes, int n_in,
                              void* d_out, int out_size) {
    const float* x    = (const float*)d_in[0];
    const void*  ei   = d_in[1];
    const float* inW  = (const float*)d_in[2];
    const float* inb  = (const float*)d_in[3];
    const float* Wq   = (const float*)d_in[4];
    const float* bq   = (const float*)d_in[5];
    const float* Wk   = (const float*)d_in[6];
    const float* bk   = (const float*)d_in[7];
    const float* Wv   = (const float*)d_in[8];
    const float* bv   = (const float*)d_in[9];
    const float* Wsk  = (const float*)d_in[10];
    const float* bsk  = (const float*)d_in[11];
    const float* lng  = (const float*)d_in[12];
    const float* lnb  = (const float*)d_in[13];
    const float* oW   = (const float*)d_in[14];
    const float* ob   = (const float*)d_in[15];
    float* out = (float*)d_out;

    detect_kernel<<<1, 1>>>(ei);
    zero_deg_kernel<<<(NN + 255) / 256, 256>>>();
    convert_kernel<<<EE / 256, 256>>>(ei);
    scan_kernel<<<1, 1024>>>();
    scatter_kernel<<<EE / 256, 256>>>();
    convw_kernel<<<(LL * 4 * 4096 + 255) / 256, 256>>>(Wq, Wk, Wv, Wsk);

    dim3 ipg((NN + 63) / 64, BB);
    input_proj_kernel<<<ipg, 256>>>(x, inW, inb);

    for (int l = 0; l < LL; l++) {
        gemm_wmma_kernel<<<BN / 64, 512>>>(l, bq + l * HH, bk + l * HH,
                                           bv + l * HH, bsk + l * HH);
        edge_node_kernel<<<(NN + 7) / 8, 256>>>(lng, lnb);
    }

    out_proj_kernel<<<(BN + 255) / 256, 256>>>(oW, ob, out);
}

// round 14
// speedup vs baseline: 3.1153x; 1.0888x over previous
#include <cuda_runtime.h>
#include <cuda_fp16.h>
#include <mma.h>
#include <math.h>

using namespace nvcuda;

#define NN 10000
#define EE 320000
#define BB 8
#define SS 12
#define HH 64
#define HEADS 4
#define CC 16
#define LL 3
#define PP 3
#define BN (BB * NN)
#define EPSF 1e-5f

__device__ __align__(16) float d_h[BN * HH];
__device__ __align__(16) __half d_h16[BN * HH];
__device__ __align__(16) __half d_q16[BN * HH];   // batch-major [b*NN+n][64]
__device__ __align__(16) __half d_s16[BN * HH];   // batch-major
// node-major: [n][b][64]
__device__ __align__(16) __half d_k16[BN * HH];
__device__ __align__(16) __half d_v16[BN * HH];
__device__ __align__(16) __half d_W16all[LL * 4 * HH * HH];
__device__ int d_src[EE];
__device__ int d_dst[EE];
__device__ int d_deg[NN];
__device__ int d_ptr[NN + 1];
__device__ int d_cnt[NN];
__device__ int d_csr_src[EE];
__device__ int d_is64;
__device__ int d_bsum[40];
__device__ int d_boff[40];

// thread 0 detects edge dtype; all threads zero the degree array
__global__ void detect_zero_kernel(const void* ei) {
    int tid = threadIdx.x;
    if (tid == 0) {
        const long long* p = (const long long*)ei;
        int is64 = 1;
        for (int i = 0; i < 64; i++) {
            long long v = p[i];
            if (v < 0 || v >= NN) { is64 = 0; break; }
        }
        d_is64 = is64;
    }
    for (int idx = tid; idx < NN; idx += 1024) d_deg[idx] = 0;
}

__global__ void convert_kernel(const void* ei) {
    int e = blockIdx.x * blockDim.x + threadIdx.x;
    if (e >= EE) return;
    int s, d;
    if (d_is64) {
        const long long* p = (const long long*)ei;
        s = (int)p[e];
        d = (int)p[EE + e];
    } else {
        const int* p = (const int*)ei;
        s = p[e];
        d = p[EE + e];
    }
    d_src[e] = s;
    d_dst[e] = d;
    atomicAdd(&d_deg[d], 1);
}

// multi-block scan, phase 1: per-block sums (40 blocks x 256)
__global__ void scan1_kernel() {
    __shared__ int wsum[8];
    int idx = blockIdx.x * 256 + threadIdx.x;
    int v = (idx < NN) ? d_deg[idx] : 0;
    int lane = threadIdx.x & 31, wid = threadIdx.x >> 5;
    int t = v;
#pragma unroll
    for (int o = 1; o < 32; o <<= 1) t += __shfl_xor_sync(0xFFFFFFFF, t, o);
    if (lane == 0) wsum[wid] = t;
    __syncthreads();
    if (threadIdx.x == 0) {
        int a = 0;
#pragma unroll
        for (int i = 0; i < 8; i++) a += wsum[i];
        d_bsum[blockIdx.x] = a;
    }
}

// phase 2: exclusive scan of the 40 block sums (1 block, 64 threads)
__global__ void scan2_kernel() {
    __shared__ int vals[64];
    int tid = threadIdx.x;
    vals[tid] = (tid < 40) ? d_bsum[tid] : 0;
    __syncthreads();
    if (tid == 0) {
        int a = 0;
        for (int i = 0; i < 40; i++) { int t = vals[i]; vals[i] = a; a += t; }
    }
    __syncthreads();
    if (tid < 40) d_boff[tid] = vals[tid];
}

// phase 3: block-local exclusive scan + offset -> d_ptr, d_cnt
__global__ void scan3_kernel() {
    __shared__ int wsum[8];
    int idx = blockIdx.x * 256 + threadIdx.x;
    int v = (idx < NN) ? d_deg[idx] : 0;
    int lane = threadIdx.x & 31, wid = threadIdx.x >> 5;
    int incl = v;
#pragma unroll
    for (int o = 1; o < 32; o <<= 1) {
        int t = __shfl_up_sync(0xFFFFFFFF, incl, o);
        if (lane >= o) incl += t;
    }
    if (lane == 31) wsum[wid] = incl;
    __syncthreads();
    if (wid == 0 && lane < 8) {
        int t = wsum[lane];
        int a = t;
#pragma unroll
        for (int o = 1; o < 8; o <<= 1) {
            int u = __shfl_up_sync(0xFF, a, o);
            if (lane >= o) a += u;
        }
        wsum[lane] = a - t;   // exclusive warp offsets
    }
    __syncthreads();
    int excl = incl - v + wsum[wid] + d_boff[blockIdx.x];
    if (idx < NN) {
        d_ptr[idx] = excl;
        d_cnt[idx] = excl;
    }
    if (idx == NN - 1) d_ptr[NN] = EE;
}

__global__ void scatter_kernel() {
    int e = blockIdx.x * blockDim.x + threadIdx.x;
    if (e >= EE) return;
    int d = d_dst[e];
    int pos = atomicAdd(&d_cnt[d], 1);
    d_csr_src[pos] = d_src[e];
}

__global__ void convw_kernel(const float* __restrict__ Wq, const float* __restrict__ Wk,
                             const float* __restrict__ Wv, const float* __restrict__ Wsk) {
    int idx = blockIdx.x * blockDim.x + threadIdx.x;
    if (idx >= LL * 4 * 4096) return;
    int l = idx >> 14;
    int sel = (idx >> 12) & 3;
    int j = idx & 4095;
    const float* W = (sel == 0) ? Wq : (sel == 1) ? Wk : (sel == 2) ? Wv : Wsk;
    d_W16all[idx] = __float2half(W[l * 4096 + j]);
}

__global__ void input_proj_kernel(const float* __restrict__ x,
                                  const float* __restrict__ inW,
                                  const float* __restrict__ inb) {
    __shared__ float xs[SS * 64];
    __shared__ float Ws[SS * HH];
    int b = blockIdx.y;
    int nb = blockIdx.x * 64;
    int tid = threadIdx.x;
    for (int idx = tid; idx < SS * HH; idx += 256) Ws[idx] = inW[idx];
    for (int idx = tid; idx < SS * 64; idx += 256) {
        int s = idx >> 6, i = idx & 63;
        int n = nb + i;
        xs[idx] = (n < NN) ? x[(size_t)b * SS * NN + s * NN + n] : 0.0f;
    }
    __syncthreads();
    int j = tid & 63;
    int i0 = (tid >> 6) * 16;
    float bj = inb[j];
    for (int ii = 0; ii < 16; ii++) {
        int i = i0 + ii;
        int n = nb + i;
        if (n >= NN) break;
        float acc = bj;
#pragma unroll
        for (int s = 0; s < SS; s++) acc += xs[s * 64 + i] * Ws[s * HH + j];
        size_t o = ((size_t)b * NN + n) * HH + j;
        d_h[o] = acc;
        d_h16[o] = __float2half(acc);
    }
}

// 512 threads = 16 warps: warp = rowtile(0-3) + 4*sel(0-3). 64 rows per block.
// All outputs fp16: q/s batch-major, k/v node-major.
__global__ void gemm_wmma_kernel(int layer,
                                 const float* __restrict__ b0, const float* __restrict__ b1,
                                 const float* __restrict__ b2, const float* __restrict__ b3) {
    __shared__ __half As[64 * 72];
    __shared__ float stage[16][256];
    int tid = threadIdx.x;
    int warp = tid >> 5;
    int lane = tid & 31;
    int rt = warp & 3;
    int wsel = warp >> 2;
    int base0 = blockIdx.x * 64;
    int base = base0 + rt * 16;

    {
        int row = tid >> 3, col = (tid & 7) * 8;
        uint4 vsrc = *(const uint4*)(d_h16 + (size_t)(base0 + row) * 64 + col);
        *(uint4*)(As + row * 72 + col) = vsrc;
    }
    __syncthreads();

    const __half* B = d_W16all + ((size_t)layer * 4 + wsel) * 4096;

    wmma::fragment<wmma::accumulator, 16, 16, 16, float> acc[4];
#pragma unroll
    for (int nt = 0; nt < 4; nt++) wmma::fill_fragment(acc[nt], 0.0f);

#pragma unroll
    for (int kk = 0; kk < 4; kk++) {
        wmma::fragment<wmma::matrix_a, 16, 16, 16, __half, wmma::row_major> a;
        wmma::load_matrix_sync(a, As + (rt * 16) * 72 + kk * 16, 72);
#pragma unroll
        for (int nt = 0; nt < 4; nt++) {
            wmma::fragment<wmma::matrix_b, 16, 16, 16, __half, wmma::row_major> b;
            wmma::load_matrix_sync(b, B + (size_t)kk * 16 * 64 + nt * 16, 64);
            wmma::mma_sync(acc[nt], a, b, acc[nt]);
        }
    }

    const float* bias = (wsel == 0) ? b0 : (wsel == 1) ? b1 : (wsel == 2) ? b2 : b3;
    float* stg = &stage[warp][0];
    int r = lane >> 1, c0 = (lane & 1) * 8;
    int gr = base + r;
    int gb = gr / NN;
    int gn = gr - gb * NN;
    __half* outp = (wsel == 0) ? d_q16 : (wsel == 1) ? d_k16 : (wsel == 2) ? d_v16 : d_s16;
    size_t rowoff = (wsel == 0 || wsel == 3) ? (size_t)gr * 64
                                             : ((size_t)gn * BB + gb) * 64;
#pragma unroll
    for (int nt = 0; nt < 4; nt++) {
        wmma::store_matrix_sync(stg, acc[nt], 16, wmma::mem_row_major);
        __syncwarp();
        int gc = nt * 16 + c0;
        float vals[8];
#pragma unroll
        for (int t = 0; t < 8; t++) vals[t] = stg[r * 16 + c0 + t] + bias[gc + t];
        __half2 h2[4];
#pragma unroll
        for (int t = 0; t < 4; t++) h2[t] = __floats2half2_rn(vals[2 * t], vals[2 * t + 1]);
        *(uint4*)(outp + rowoff + gc) = *(uint4*)h2;
        __syncwarp();
    }
}

// warp per NODE. lane = b*4 + head. Lane owns head's 16 dims for batch b.
// CSR indices software-pipelined (prefetched one iteration ahead) so the
// index load overlaps the k/v gathers of the previous iteration.
__global__ void __launch_bounds__(256) edge_node_kernel(const float* __restrict__ g,
                                                        const float* __restrict__ bta) {
    int n = blockIdx.x * 8 + (threadIdx.x >> 5);
    int lane = threadIdx.x & 31;
    int b = lane >> 2;
    int head = lane & 3;
    int rowbase = (b * NN + n) * HH + head * CC;   // batch-major (h fp32)
    int kvoff = b * HH + head * CC;                // within node block (halves)

    // q in fp16: 16 halves = 2 uint4
    float q[16];
    {
        uint4 qa = *(const uint4*)(d_q16 + rowbase);
        uint4 qb = *(const uint4*)(d_q16 + rowbase + 8);
        const __half2* qh = (const __half2*)&qa;
#pragma unroll
        for (int t = 0; t < 4; t++) {
            float2 f = __half22float2(qh[t]);
            q[2 * t] = f.x; q[2 * t + 1] = f.y;
        }
        qh = (const __half2*)&qb;
#pragma unroll
        for (int t = 0; t < 4; t++) {
            float2 f = __half22float2(qh[t]);
            q[8 + 2 * t] = f.x; q[8 + 2 * t + 1] = f.y;
        }
    }

    int start = d_ptr[n];
    int end = d_ptr[n + 1];

    float ac[16];
#pragma unroll
    for (int t = 0; t < 16; t++) ac[t] = 0.f;
    float den = 0.f;

    if (start < end) {
        int s0n = d_csr_src[start];
        int s1n = d_csr_src[(start + 1 < end) ? (start + 1) : start];
        for (int i = start; i < end; i += 2) {
            int s0 = s0n, s1 = s1n;
            bool va1 = (i + 1 < end);
            int nj0 = (i + 2 < end) ? (i + 2) : i;
            int nj1 = (i + 3 < end) ? (i + 3) : i;
            s0n = d_csr_src[nj0];
            s1n = d_csr_src[nj1];
            size_t a0 = (size_t)s0 * 512 + kvoff;
            size_t a1 = (size_t)s1 * 512 + kvoff;
            uint4 k0a = *(const uint4*)(d_k16 + a0);
            uint4 k0b = *(const uint4*)(d_k16 + a0 + 8);
            uint4 v0a = *(const uint4*)(d_v16 + a0);
            uint4 v0b = *(const uint4*)(d_v16 + a0 + 8);
            uint4 k1a = *(const uint4*)(d_k16 + a1);
            uint4 k1b = *(const uint4*)(d_k16 + a1 + 8);
            uint4 v1a = *(const uint4*)(d_v16 + a1);
            uint4 v1b = *(const uint4*)(d_v16 + a1 + 8);

            {
                const __half2* kh = (const __half2*)&k0a;
                float p = 0.f;
#pragma unroll
                for (int t = 0; t < 4; t++) {
                    float2 f = __half22float2(kh[t]);
                    p += q[2 * t] * f.x + q[2 * t + 1] * f.y;
                }
                kh = (const __half2*)&k0b;
#pragma unroll
                for (int t = 0; t < 4; t++) {
                    float2 f = __half22float2(kh[t]);
                    p += q[8 + 2 * t] * f.x + q[8 + 2 * t + 1] * f.y;
                }
                float wt = __expf(p * 0.25f);
                den += wt;
                const __half2* vh = (const __half2*)&v0a;
#pragma unroll
                for (int t = 0; t < 4; t++) {
                    float2 f = __half22float2(vh[t]);
                    ac[2 * t] += wt * f.x; ac[2 * t + 1] += wt * f.y;
                }
                vh = (const __half2*)&v0b;
#pragma unroll
                for (int t = 0; t < 4; t++) {
                    float2 f = __half22float2(vh[t]);
                    ac[8 + 2 * t] += wt * f.x; ac[8 + 2 * t + 1] += wt * f.y;
                }
            }
            {
                const __half2* kh = (const __half2*)&k1a;
                float p = 0.f;
#pragma unroll
                for (int t = 0; t < 4; t++) {
                    float2 f = __half22float2(kh[t]);
                    p += q[2 * t] * f.x + q[2 * t + 1] * f.y;
                }
                kh = (const __half2*)&k1b;
#pragma unroll
                for (int t = 0; t < 4; t++) {
                    float2 f = __half22float2(kh[t]);
                    p += q[8 + 2 * t] * f.x + q[8 + 2 * t + 1] * f.y;
                }
                float wt = va1 ? __expf(p * 0.25f) : 0.f;
                den += wt;
                const __half2* vh = (const __half2*)&v1a;
#pragma unroll
                for (int t = 0; t < 4; t++) {
                    float2 f = __half22float2(vh[t]);
                    ac[2 * t] += wt * f.x; ac[2 * t + 1] += wt * f.y;
                }
                vh = (const __half2*)&v1b;
#pragma unroll
                for (int t = 0; t < 4; t++) {
                    float2 f = __half22float2(vh[t]);
                    ac[8 + 2 * t] += wt * f.x; ac[8 + 2 * t + 1] += wt * f.y;
                }
            }
        }
    }

    float inv = (den > 0.f) ? (1.0f / den) : 0.f;
    float hv[16], sv[16];
    {
        const float4* hp = (const float4*)(d_h + rowbase);
#pragma unroll
        for (int t = 0; t < 4; t++) {
            float4 f = hp[t];
            hv[4 * t] = f.x; hv[4 * t + 1] = f.y; hv[4 * t + 2] = f.z; hv[4 * t + 3] = f.w;
        }
        uint4 sa = *(const uint4*)(d_s16 + rowbase);
        uint4 sb = *(const uint4*)(d_s16 + rowbase + 8);
        const __half2* sh = (const __half2*)&sa;
#pragma unroll
        for (int t = 0; t < 4; t++) {
            float2 f = __half22float2(sh[t]);
            sv[2 * t] = f.x; sv[2 * t + 1] = f.y;
        }
        sh = (const __half2*)&sb;
#pragma unroll
        for (int t = 0; t < 4; t++) {
            float2 f = __half22float2(sh[t]);
            sv[8 + 2 * t] = f.x; sv[8 + 2 * t + 1] = f.y;
        }
    }

    float tv[16];
    float sum = 0.f, sq = 0.f;
#pragma unroll
    for (int t = 0; t < 16; t++) {
        tv[t] = hv[t] + ac[t] * inv + sv[t];
        sum += tv[t];
        sq += tv[t] * tv[t];
    }
    sum += __shfl_xor_sync(0xFFFFFFFF, sum, 1);
    sq  += __shfl_xor_sync(0xFFFFFFFF, sq, 1);
    sum += __shfl_xor_sync(0xFFFFFFFF, sum, 2);
    sq  += __shfl_xor_sync(0xFFFFFFFF, sq, 2);

    float mean = sum * (1.0f / 64.0f);
    float var = sq * (1.0f / 64.0f) - mean * mean;
    float rs = rsqrtf(var + EPSF);

    float ov[16];
#pragma unroll
    for (int t = 0; t < 4; t++) {
        float4 gv = *(const float4*)(g + head * CC + 4 * t);
        float4 ev = *(const float4*)(bta + head * CC + 4 * t);
        ov[4 * t]     = (tv[4 * t]     - mean) * rs * gv.x + ev.x;
        ov[4 * t + 1] = (tv[4 * t + 1] - mean) * rs * gv.y + ev.y;
        ov[4 * t + 2] = (tv[4 * t + 2] - mean) * rs * gv.z + ev.z;
        ov[4 * t + 3] = (tv[4 * t + 3] - mean) * rs * gv.w + ev.w;
    }

    float4* hp = (float4*)(d_h + rowbase);
#pragma unroll
    for (int t = 0; t < 4; t++)
        hp[t] = make_float4(ov[4 * t], ov[4 * t + 1], ov[4 * t + 2], ov[4 * t + 3]);
    __half2 hh[8];
#pragma unroll
    for (int t = 0; t < 8; t++) hh[t] = __floats2half2_rn(ov[2 * t], ov[2 * t + 1]);
    *(uint4*)(d_h16 + rowbase)     = *(uint4*)&hh[0];
    *(uint4*)(d_h16 + rowbase + 8) = *(uint4*)&hh[4];
}

__global__ void out_proj_kernel(const float* __restrict__ oW,
                                const float* __restrict__ ob,
                                float* __restrict__ out) {
    int t = blockIdx.x * blockDim.x + threadIdx.x;
    if (t >= BN) return;
    int b = t / NN, n = t % NN;
    const float4* hr = (const float4*)(d_h + (size_t)t * 64);
    float a0 = ob[0], a1 = ob[1], a2 = ob[2];
#pragma unroll
    for (int i = 0; i < 16; i++) {
        float4 hv = hr[i];
        int h0 = i * 4;
        a0 += hv.x * oW[(h0 + 0) * PP + 0]; a1 += hv.x * oW[(h0 + 0) * PP + 1]; a2 += hv.x * oW[(h0 + 0) * PP + 2];
        a0 += hv.y * oW[(h0 + 1) * PP + 0]; a1 += hv.y * oW[(h0 + 1) * PP + 1]; a2 += hv.y * oW[(h0 + 1) * PP + 2];
        a0 += hv.z * oW[(h0 + 2) * PP + 0]; a1 += hv.z * oW[(h0 + 2) * PP + 1]; a2 += hv.z * oW[(h0 + 2) * PP + 2];
        a0 += hv.w * oW[(h0 + 3) * PP + 0]; a1 += hv.w * oW[(h0 + 3) * PP + 1]; a2 += hv.w * oW[(h0 + 3) * PP + 2];
    }
    out[(size_t)b * PP * NN + 0 * NN + n] = a0;
    out[(size_t)b * PP * NN + 1 * NN + n] = a1;
    out[(size_t)b * PP * NN + 2 * NN + n] = a2;
}

extern "C" void kernel_launch(void* const* d_in, const int* in_sizes, int n_in,
                              void* d_out, int out_size) {
    const float* x    = (const float*)d_in[0];
    const void*  ei   = d_in[1];
    const float* inW  = (const float*)d_in[2];
    const float* inb  = (const float*)d_in[3];
    const float* Wq   = (const float*)d_in[4];
    const float* bq   = (const float*)d_in[5];
    const float* Wk   = (const float*)d_in[6];
    const float* bk   = (const float*)d_in[7];
    const float* Wv   = (const float*)d_in[8];
    const float* bv   = (const float*)d_in[9];
    const float* Wsk  = (const float*)d_in[10];
    const float* bsk  = (const float*)d_in[11];
    const float* lng  = (const float*)d_in[12];
    const float* lnb  = (const float*)d_in[13];
    const float* oW   = (const float*)d_in[14];
    const float* ob   = (const float*)d_in[15];
    float* out = (float*)d_out;

    detect_zero_kernel<<<1, 1024>>>(ei);
    convert_kernel<<<EE / 256, 256>>>(ei);
    scan1_kernel<<<40, 256>>>();
    scan2_kernel<<<1, 64>>>();
    scan3_kernel<<<40, 256>>>();
    scatter_kernel<<<EE / 256, 256>>>();
    convw_kernel<<<(LL * 4 * 4096 + 255) / 256, 256>>>(Wq, Wk, Wv, Wsk);

    dim3 ipg((NN + 63) / 64, BB);
    input_proj_kernel<<<ipg, 256>>>(x, inW, inb);

    for (int l = 0; l < LL; l++) {
        gemm_wmma_kernel<<<BN / 64, 512>>>(l, bq + l * HH, bk + l * HH,
                                           bv + l * HH, bsk + l * HH);
        edge_node_kernel<<<(NN + 7) / 8, 256>>>(lng, lnb);
    }

    out_proj_kernel<<<(BN + 255) / 256, 256>>>(oW, ob, out);
}